// round 2
// baseline (speedup 1.0000x reference)
#include <cuda_runtime.h>
#include <math.h>

#define NN   100000
#define N2   (2 * NN)
#define EE   1200000
#define HH   64
#define EMBD 100
#define BB   4096

// ---------------- scratch (device globals; no allocation allowed) ----------
__device__ float g_h  [N2 * HH];
__device__ float g_hm [N2 * HH];
__device__ float g_agg[N2 * HH];
__device__ float g_cat[BB * 2 * HH];
__device__ float g_hid[BB * HH];
__device__ float g_loss;

// -------- projection (both graphs): h[n] = emb_table[ind[n]] @ Wp + bp -----
__global__ __launch_bounds__(256) void proj_kernel(
    const float* __restrict__ emb,
    const int* __restrict__ ind0, const int* __restrict__ ind1,
    const float* __restrict__ Wp, const float* __restrict__ bp)
{
    const int j   = threadIdx.x & 63;
    const int grp = threadIdx.x >> 6;      // 4 nodes per block-iteration
    float wc[EMBD];
#pragma unroll
    for (int k = 0; k < EMBD; k++) wc[k] = Wp[k * HH + j];
    const float bj = bp[j];

    __shared__ __align__(16) float s_e[4][EMBD];
    const int ntiles = (N2 + 3) / 4;
    for (int tile = blockIdx.x; tile < ntiles; tile += gridDim.x) {
        const int node = tile * 4 + grp;
        __syncthreads();
        if (node < N2) {
            const int row = (node < NN) ? ind0[node] : ind1[node - NN];
            for (int k = j; k < EMBD; k += 64) s_e[grp][k] = emb[row * EMBD + k];
        }
        __syncthreads();
        if (node < N2) {
            float a0 = bj, a1 = 0.0f;
#pragma unroll
            for (int k = 0; k < EMBD; k += 8) {
                const float4 v = *reinterpret_cast<const float4*>(&s_e[grp][k]);
                const float4 w = *reinterpret_cast<const float4*>(&s_e[grp][k + 4]);
                a0 = fmaf(v.x, wc[k + 0], a0);
                a1 = fmaf(v.y, wc[k + 1], a1);
                a0 = fmaf(v.z, wc[k + 2], a0);
                a1 = fmaf(v.w, wc[k + 3], a1);
                a0 = fmaf(w.x, wc[k + 4], a0);
                a1 = fmaf(w.y, wc[k + 5], a1);
                a0 = fmaf(w.z, wc[k + 6], a0);
                a1 = fmaf(w.w, wc[k + 7], a1);
            }
            {   // EMBD=100 => last 4
                const float4 v = *reinterpret_cast<const float4*>(&s_e[grp][96]);
                a0 = fmaf(v.x, wc[96], a0);
                a1 = fmaf(v.y, wc[97], a1);
                a0 = fmaf(v.z, wc[98], a0);
                a1 = fmaf(v.w, wc[99], a1);
            }
            g_h[node * HH + j] = a0 + a1;
        }
    }
}

// ------- message precompute (both graphs): hm = h @ Wm + bm ; agg = 0 ------
__global__ __launch_bounds__(256) void msg_kernel(
    const float* __restrict__ Wm, const float* __restrict__ bm)
{
    const int j   = threadIdx.x & 63;
    const int grp = threadIdx.x >> 6;
    float wc[HH];
#pragma unroll
    for (int k = 0; k < HH; k++) wc[k] = Wm[k * HH + j];
    const float bj = bm[j];

    __shared__ __align__(16) float s_h[4][HH];
    const int ntiles = N2 / 4;             // 200000 % 4 == 0
    for (int tile = blockIdx.x; tile < ntiles; tile += gridDim.x) {
        const int node = tile * 4 + grp;
        __syncthreads();
        s_h[grp][j] = g_h[node * HH + j];
        __syncthreads();
        float a0 = bj, a1 = 0.0f;
#pragma unroll
        for (int k = 0; k < HH; k += 8) {
            const float4 v = *reinterpret_cast<const float4*>(&s_h[grp][k]);
            const float4 w = *reinterpret_cast<const float4*>(&s_h[grp][k + 4]);
            a0 = fmaf(v.x, wc[k + 0], a0);
            a1 = fmaf(v.y, wc[k + 1], a1);
            a0 = fmaf(v.z, wc[k + 2], a0);
            a1 = fmaf(v.w, wc[k + 3], a1);
            a0 = fmaf(w.x, wc[k + 4], a0);
            a1 = fmaf(w.y, wc[k + 5], a1);
            a0 = fmaf(w.z, wc[k + 6], a0);
            a1 = fmaf(w.w, wc[k + 7], a1);
        }
        g_hm [node * HH + j] = a0 + a1;
        g_agg[node * HH + j] = 0.0f;
    }
}

// ---- scatter-add (both graphs): agg[tgt] += hm[src] over all 2E edges -----
__global__ __launch_bounds__(256) void scatter_kernel(
    const int* __restrict__ adj0, const int* __restrict__ adj1)
{
    const int idx = blockIdx.x * 256 + threadIdx.x;   // < 2*EE*16
    const int e = idx >> 4;
    const int q = idx & 15;
    int src, tgt;
    if (e < EE) {
        const int2 st = reinterpret_cast<const int2*>(adj0)[e];
        src = st.x;       tgt = st.y;
    } else {
        const int2 st = reinterpret_cast<const int2*>(adj1)[e - EE];
        src = st.x + NN;  tgt = st.y + NN;
    }
    const float4 v = *reinterpret_cast<const float4*>(g_hm + (size_t)src * HH + q * 4);
    float* dst = g_agg + (size_t)tgt * HH + q * 4;
    asm volatile("red.global.add.v4.f32 [%0], {%1,%2,%3,%4};"
                 :: "l"(dst), "f"(v.x), "f"(v.y), "f"(v.z), "f"(v.w)
                 : "memory");
}

// ----------- GRU cell over all 2N nodes (in-place on g_h) ------------------
__global__ __launch_bounds__(192, 2) void gru_kernel(
    const float* __restrict__ Wih, const float* __restrict__ Whh,
    const float* __restrict__ bih, const float* __restrict__ bhh)
{
    const int j = threadIdx.x;               // 0..191 : one gate column
    float wi[HH], wh[HH];
#pragma unroll
    for (int k = 0; k < HH; k++) {
        wi[k] = Wih[k * 192 + j];
        wh[k] = Whh[k * 192 + j];
    }
    const float bi = bih[j], bh = bhh[j];

    const int T = 6;                         // nodes per tile (even)
    __shared__ __align__(16) float s_x[T * HH];
    __shared__ __align__(16) float s_h[T * HH];
    __shared__ float s_gi[T * 192];
    __shared__ float s_gh[T * 192];

    const int ntiles = (N2 + T - 1) / T;
    for (int tile = blockIdx.x; tile < ntiles; tile += gridDim.x) {
        const int base = tile * T;
        const int cnt  = min(T, N2 - base);
        __syncthreads();
        for (int i = j; i < T * HH; i += 192) {
            const bool ok = (i < cnt * HH);
            s_x[i] = ok ? g_agg[base * HH + i] : 0.0f;
            s_h[i] = ok ? g_h  [base * HH + i] : 0.0f;
        }
        __syncthreads();
#pragma unroll
        for (int t = 0; t < T; t += 2) {     // two nodes at once -> 4 chains
            float ai0 = bi, ah0 = bh, ai1 = bi, ah1 = bh;
            const float* xr0 = s_x + t * HH;
            const float* hr0 = s_h + t * HH;
            const float* xr1 = xr0 + HH;
            const float* hr1 = hr0 + HH;
#pragma unroll
            for (int k = 0; k < HH; k += 4) {
                const float4 x0 = *reinterpret_cast<const float4*>(xr0 + k);
                const float4 h0 = *reinterpret_cast<const float4*>(hr0 + k);
                const float4 x1 = *reinterpret_cast<const float4*>(xr1 + k);
                const float4 h1 = *reinterpret_cast<const float4*>(hr1 + k);
                ai0 = fmaf(x0.x, wi[k + 0], ai0);
                ah0 = fmaf(h0.x, wh[k + 0], ah0);
                ai1 = fmaf(x1.x, wi[k + 0], ai1);
                ah1 = fmaf(h1.x, wh[k + 0], ah1);
                ai0 = fmaf(x0.y, wi[k + 1], ai0);
                ah0 = fmaf(h0.y, wh[k + 1], ah0);
                ai1 = fmaf(x1.y, wi[k + 1], ai1);
                ah1 = fmaf(h1.y, wh[k + 1], ah1);
                ai0 = fmaf(x0.z, wi[k + 2], ai0);
                ah0 = fmaf(h0.z, wh[k + 2], ah0);
                ai1 = fmaf(x1.z, wi[k + 2], ai1);
                ah1 = fmaf(h1.z, wh[k + 2], ah1);
                ai0 = fmaf(x0.w, wi[k + 3], ai0);
                ah0 = fmaf(h0.w, wh[k + 3], ah0);
                ai1 = fmaf(x1.w, wi[k + 3], ai1);
                ah1 = fmaf(h1.w, wh[k + 3], ah1);
            }
            s_gi[t * 192 + j]       = ai0;
            s_gh[t * 192 + j]       = ah0;
            s_gi[(t + 1) * 192 + j] = ai1;
            s_gh[(t + 1) * 192 + j] = ah1;
        }
        __syncthreads();
        for (int o = j; o < cnt * HH; o += 192) {
            const int t = o >> 6, c = o & 63;
            const float r = 1.0f / (1.0f + __expf(-(s_gi[t*192 + c]       + s_gh[t*192 + c])));
            const float z = 1.0f / (1.0f + __expf(-(s_gi[t*192 + 64 + c]  + s_gh[t*192 + 64 + c])));
            float nx = s_gi[t*192 + 128 + c] + r * s_gh[t*192 + 128 + c];
            nx = fminf(fmaxf(nx, -15.0f), 15.0f);
            const float e2 = __expf(-2.0f * nx);
            const float n  = (1.0f - e2) / (1.0f + e2);
            g_h[base * HH + o] = (1.0f - z) * n + z * s_h[o];
        }
    }
}

// ---------------- gather propagated nodes into concat buffer ---------------
__global__ void gather_kernel(const int* __restrict__ prop0,
                              const int* __restrict__ prop1)
{
    const int i = blockIdx.x * blockDim.x + threadIdx.x;
    if (i >= 2 * BB * HH) return;
    const int half = i / (BB * HH);          // 0: graph0, 1: graph1
    const int r    = i - half * (BB * HH);
    const int b = r >> 6, j = r & 63;
    const int node = half ? (prop1[b] + NN) : prop0[b];
    g_cat[b * (2 * HH) + half * HH + j] = g_h[node * HH + j];
}

// ---------------- hidden = relu(cat @ W1 + b1) -----------------------------
__global__ __launch_bounds__(256) void hidden_kernel(
    const float* __restrict__ W1, const float* __restrict__ b1)
{
    const int j   = threadIdx.x & 63;
    const int grp = threadIdx.x >> 6;
    float wc[2 * HH];
#pragma unroll
    for (int k = 0; k < 2 * HH; k++) wc[k] = W1[k * HH + j];
    const float bj = b1[j];

    __shared__ __align__(16) float s_c[4][2 * HH];
    const int ntiles = BB / 4;
    for (int tile = blockIdx.x; tile < ntiles; tile += gridDim.x) {
        const int b = tile * 4 + grp;
        __syncthreads();
        s_c[grp][j]      = g_cat[b * 128 + j];
        s_c[grp][j + 64] = g_cat[b * 128 + j + 64];
        __syncthreads();
        float a0 = bj, a1 = 0.0f;
#pragma unroll
        for (int k = 0; k < 2 * HH; k += 8) {
            const float4 v = *reinterpret_cast<const float4*>(&s_c[grp][k]);
            const float4 w = *reinterpret_cast<const float4*>(&s_c[grp][k + 4]);
            a0 = fmaf(v.x, wc[k + 0], a0);
            a1 = fmaf(v.y, wc[k + 1], a1);
            a0 = fmaf(v.z, wc[k + 2], a0);
            a1 = fmaf(v.w, wc[k + 3], a1);
            a0 = fmaf(w.x, wc[k + 4], a0);
            a1 = fmaf(w.y, wc[k + 5], a1);
            a0 = fmaf(w.z, wc[k + 6], a0);
            a1 = fmaf(w.w, wc[k + 7], a1);
        }
        g_hid[b * HH + j] = fmaxf(a0 + a1, 0.0f);
    }
}

// ---------------- head: z, probs, loss -------------------------------------
__global__ void zero_loss_kernel() { g_loss = 0.0f; }

__global__ void head_kernel(const float* __restrict__ W2, const float* __restrict__ b2,
                            const int* __restrict__ labels, float* __restrict__ out)
{
    const int warp = (blockIdx.x * blockDim.x + threadIdx.x) >> 5;
    const int lane = threadIdx.x & 31;
    if (warp >= BB) return;
    float acc = fmaf(g_hid[warp * HH + lane],      W2[lane],      0.0f);
    acc       = fmaf(g_hid[warp * HH + lane + 32], W2[lane + 32], acc);
#pragma unroll
    for (int s = 16; s; s >>= 1) acc += __shfl_xor_sync(0xffffffffu, acc, s);
    if (lane == 0) {
        const float z = acc + b2[0];
        out[warp] = 1.0f / (1.0f + __expf(-z));
        const float y = (float)labels[warp];
        const float t = (y > 0.5f) ? -z : z;           // y*sp(-z)+(1-y)*sp(z)
        const float sp = fmaxf(t, 0.0f) + log1pf(__expf(-fabsf(t)));
        atomicAdd(&g_loss, sp);
    }
}

__global__ void finalize_kernel(float* __restrict__ out)
{
    out[BB] = g_loss * (1.0f / (float)BB);
}

// ---------------------------------------------------------------------------
extern "C" void kernel_launch(void* const* d_in, const int* in_sizes, int n_in,
                              void* d_out, int out_size)
{
    const int*   emb_ind[2] = {(const int*)d_in[0],  (const int*)d_in[1]};
    const int*   adj[2]     = {(const int*)d_in[2],  (const int*)d_in[3]};
    const int*   prop[2]    = {(const int*)d_in[4],  (const int*)d_in[5]};
    const int*   labels     =  (const int*)d_in[6];
    const float* emb_table  =  (const float*)d_in[7];
    const float* Wp         =  (const float*)d_in[8];
    const float* bp         =  (const float*)d_in[9];
    const float* Wm[2]  = {(const float*)d_in[10], (const float*)d_in[16]};
    const float* bm[2]  = {(const float*)d_in[11], (const float*)d_in[17]};
    const float* Wih[2] = {(const float*)d_in[12], (const float*)d_in[18]};
    const float* Whh[2] = {(const float*)d_in[13], (const float*)d_in[19]};
    const float* bih[2] = {(const float*)d_in[14], (const float*)d_in[20]};
    const float* bhh[2] = {(const float*)d_in[15], (const float*)d_in[21]};
    const float* W1 = (const float*)d_in[22];
    const float* b1 = (const float*)d_in[23];
    const float* W2 = (const float*)d_in[24];
    const float* b2 = (const float*)d_in[25];
    float* out = (float*)d_out;

    proj_kernel<<<2048, 256>>>(emb_table, emb_ind[0], emb_ind[1], Wp, bp);
    for (int l = 0; l < 2; l++) {
        for (int t = 0; t < 3; t++) {
            msg_kernel<<<2048, 256>>>(Wm[l], bm[l]);
            scatter_kernel<<<(2 * EE * 16) / 256, 256>>>(adj[0], adj[1]);
            gru_kernel<<<2048, 192>>>(Wih[l], Whh[l], bih[l], bhh[l]);
        }
    }
    gather_kernel<<<(2 * BB * HH + 255) / 256, 256>>>(prop[0], prop[1]);
    hidden_kernel<<<512, 256>>>(W1, b1);
    zero_loss_kernel<<<1, 1>>>();
    head_kernel<<<(BB * 32 + 255) / 256, 256>>>(W2, b2, labels, out);
    finalize_kernel<<<1, 1>>>(out);
    (void)in_sizes; (void)n_in; (void)out_size;
}

// round 3
// speedup vs baseline: 1.0539x; 1.0539x over previous
#include <cuda_runtime.h>
#include <math.h>

#define NN   100000
#define N2   (2 * NN)
#define EE   1200000
#define HH   64
#define EMBD 100
#define BB   4096

// ---------------- scratch (device globals; no allocation allowed) ----------
__device__ float g_h  [N2 * HH];
__device__ float g_agg[N2 * HH];
__device__ float g_deg[N2];
__device__ float g_Wf [2 * HH * 192];   // fused Wm@Wih per layer
__device__ float g_bf [2 * 192];        // fused bm@Wih per layer
__device__ float g_cat[BB * 2 * HH];
__device__ float g_hid[BB * HH];
__device__ float g_loss;

// ---------------- init: zero agg, deg, loss --------------------------------
__global__ void init_kernel()
{
    const int idx = blockIdx.x * 256 + threadIdx.x;
    if (idx < N2 * HH / 4) reinterpret_cast<float4*>(g_agg)[idx] = make_float4(0, 0, 0, 0);
    if (idx < N2) g_deg[idx] = 0.0f;
    if (idx == 0) g_loss = 0.0f;
}

// ---------------- degree count (both graphs) -------------------------------
__global__ void deg_kernel(const int* __restrict__ adj0, const int* __restrict__ adj1)
{
    const int e = blockIdx.x * 256 + threadIdx.x;
    if (e >= 2 * EE) return;
    const int tgt = (e < EE) ? adj0[2 * e + 1] : (adj1[2 * (e - EE) + 1] + NN);
    atomicAdd(&g_deg[tgt], 1.0f);
}

// ------------- fuse weights: Wf = Wm@Wih, bf = bm@Wih ----------------------
__global__ __launch_bounds__(192) void fuse_kernel(
    const float* __restrict__ Wm0, const float* __restrict__ Wih0, const float* __restrict__ bm0,
    const float* __restrict__ Wm1, const float* __restrict__ Wih1, const float* __restrict__ bm1)
{
    const int k = blockIdx.x;           // 0..64 (64 => bias row)
    const int l = blockIdx.y;
    const int j = threadIdx.x;
    const float* Wm  = l ? Wm1  : Wm0;
    const float* Wih = l ? Wih1 : Wih0;
    const float* bm  = l ? bm1  : bm0;
    __shared__ float row[HH];
    if (j < HH) row[j] = (k < HH) ? Wm[k * HH + j] : bm[j];
    __syncthreads();
    float acc = 0.0f;
#pragma unroll
    for (int m = 0; m < HH; m++) acc = fmaf(row[m], Wih[m * 192 + j], acc);
    if (k < HH) g_Wf[l * HH * 192 + k * 192 + j] = acc;
    else        g_bf[l * 192 + j] = acc;
}

// -------- projection (both graphs): h[n] = emb_table[ind[n]] @ Wp + bp -----
__global__ __launch_bounds__(256) void proj_kernel(
    const float* __restrict__ emb,
    const int* __restrict__ ind0, const int* __restrict__ ind1,
    const float* __restrict__ Wp, const float* __restrict__ bp)
{
    const int j   = threadIdx.x & 63;
    const int grp = threadIdx.x >> 6;
    float wc[EMBD];
#pragma unroll
    for (int k = 0; k < EMBD; k++) wc[k] = Wp[k * HH + j];
    const float bj = bp[j];

    __shared__ __align__(16) float s_e[4][EMBD];
    const int ntiles = N2 / 4;
    for (int tile = blockIdx.x; tile < ntiles; tile += gridDim.x) {
        const int node = tile * 4 + grp;
        __syncthreads();
        {
            const int row = (node < NN) ? ind0[node] : ind1[node - NN];
            for (int k = j; k < EMBD; k += 64) s_e[grp][k] = emb[row * EMBD + k];
        }
        __syncthreads();
        float a0 = bj, a1 = 0.0f;
#pragma unroll
        for (int k = 0; k < 96; k += 8) {
            const float4 v = *reinterpret_cast<const float4*>(&s_e[grp][k]);
            const float4 w = *reinterpret_cast<const float4*>(&s_e[grp][k + 4]);
            a0 = fmaf(v.x, wc[k + 0], a0);
            a1 = fmaf(v.y, wc[k + 1], a1);
            a0 = fmaf(v.z, wc[k + 2], a0);
            a1 = fmaf(v.w, wc[k + 3], a1);
            a0 = fmaf(w.x, wc[k + 4], a0);
            a1 = fmaf(w.y, wc[k + 5], a1);
            a0 = fmaf(w.z, wc[k + 6], a0);
            a1 = fmaf(w.w, wc[k + 7], a1);
        }
        {
            const float4 v = *reinterpret_cast<const float4*>(&s_e[grp][96]);
            a0 = fmaf(v.x, wc[96], a0);
            a1 = fmaf(v.y, wc[97], a1);
            a0 = fmaf(v.z, wc[98], a0);
            a1 = fmaf(v.w, wc[99], a1);
        }
        g_h[node * HH + j] = a0 + a1;
    }
}

// ---- scatter-add (both graphs): agg[tgt] += h[src] over all 2E edges ------
// 16 lanes per edge; adj loaded once per group and shuffled.
__global__ __launch_bounds__(256) void scatter_kernel(
    const int* __restrict__ adj0, const int* __restrict__ adj1)
{
    const int idx  = blockIdx.x * 256 + threadIdx.x;   // < 2*EE*16
    const int e    = idx >> 4;
    const int q    = idx & 15;
    const int lane = threadIdx.x & 31;
    long long ev = 0;
    if ((lane & 15) == 0) {
        ev = (e < EE) ? reinterpret_cast<const long long*>(adj0)[e]
                      : reinterpret_cast<const long long*>(adj1)[e - EE];
    }
    ev = __shfl_sync(0xffffffffu, ev, lane & 16);
    const int off = (e < EE) ? 0 : NN;
    const int src = (int)(ev & 0xffffffffll) + off;
    const int tgt = (int)(ev >> 32) + off;
    const float4 v = *reinterpret_cast<const float4*>(g_h + (size_t)src * HH + q * 4);
    float* dst = g_agg + (size_t)tgt * HH + q * 4;
    asm volatile("red.global.add.v4.f32 [%0], {%1,%2,%3,%4};"
                 :: "l"(dst), "f"(v.x), "f"(v.y), "f"(v.z), "f"(v.w)
                 : "memory");
}

// ----------- GRU cell over all 2N nodes (in-place on g_h) ------------------
// gi = S@Wf + deg*bf + bih ; gh = h@Whh + bhh
__global__ __launch_bounds__(192, 2) void gru_kernel(
    const float* __restrict__ Whh, const float* __restrict__ bih,
    const float* __restrict__ bhh, int layer)
{
    const int j = threadIdx.x;               // gate column
    const float* Wf = g_Wf + layer * HH * 192;
    float wf[HH], wh[HH];
#pragma unroll
    for (int k = 0; k < HH; k++) {
        wf[k] = Wf [k * 192 + j];
        wh[k] = Whh[k * 192 + j];
    }
    const float bfj = g_bf[layer * 192 + j];
    const float bij = bih[j], bhj = bhh[j];

    const int T = 8;
    __shared__ __align__(16) float s_x[T * HH];
    __shared__ __align__(16) float s_h[T * HH];
    __shared__ float s_d[T];
    __shared__ float s_gi[T * 192];
    __shared__ float s_gh[T * 192];

    const int ntiles = N2 / T;               // 200000 % 8 == 0
    for (int tile = blockIdx.x; tile < ntiles; tile += gridDim.x) {
        const int base = tile * T;
        __syncthreads();
        for (int i = j; i < T * HH; i += 192) {
            s_x[i] = g_agg[base * HH + i];
            s_h[i] = g_h  [base * HH + i];
            g_agg[base * HH + i] = 0.0f;     // pre-zero for next scatter
        }
        if (j < T) s_d[j] = g_deg[base + j];
        __syncthreads();
#pragma unroll
        for (int t = 0; t < T; t++) {
            float ai = fmaf(s_d[t], bfj, bij);
            float ah = bhj;
            const float* xr = s_x + t * HH;
            const float* hr = s_h + t * HH;
#pragma unroll
            for (int k = 0; k < HH; k += 4) {
                const float4 x4 = *reinterpret_cast<const float4*>(xr + k);
                const float4 h4 = *reinterpret_cast<const float4*>(hr + k);
                ai = fmaf(x4.x, wf[k + 0], ai);
                ah = fmaf(h4.x, wh[k + 0], ah);
                ai = fmaf(x4.y, wf[k + 1], ai);
                ah = fmaf(h4.y, wh[k + 1], ah);
                ai = fmaf(x4.z, wf[k + 2], ai);
                ah = fmaf(h4.z, wh[k + 2], ah);
                ai = fmaf(x4.w, wf[k + 3], ai);
                ah = fmaf(h4.w, wh[k + 3], ah);
            }
            s_gi[t * 192 + j] = ai;
            s_gh[t * 192 + j] = ah;
        }
        __syncthreads();
        for (int o = j; o < T * HH; o += 192) {
            const int t = o >> 6, c = o & 63;
            const float r = 1.0f / (1.0f + __expf(-(s_gi[t*192 + c]       + s_gh[t*192 + c])));
            const float z = 1.0f / (1.0f + __expf(-(s_gi[t*192 + 64 + c]  + s_gh[t*192 + 64 + c])));
            float nx = s_gi[t*192 + 128 + c] + r * s_gh[t*192 + 128 + c];
            nx = fminf(fmaxf(nx, -15.0f), 15.0f);
            const float e2 = __expf(-2.0f * nx);
            const float n  = (1.0f - e2) / (1.0f + e2);
            g_h[base * HH + o] = (1.0f - z) * n + z * s_h[o];
        }
    }
}

// ---------------- gather propagated nodes into concat buffer ---------------
__global__ void gather_kernel(const int* __restrict__ prop0,
                              const int* __restrict__ prop1)
{
    const int i = blockIdx.x * blockDim.x + threadIdx.x;
    if (i >= 2 * BB * HH) return;
    const int half = i / (BB * HH);
    const int r    = i - half * (BB * HH);
    const int b = r >> 6, j = r & 63;
    const int node = half ? (prop1[b] + NN) : prop0[b];
    g_cat[b * (2 * HH) + half * HH + j] = g_h[node * HH + j];
}

// ---------------- hidden = relu(cat @ W1 + b1) -----------------------------
__global__ __launch_bounds__(256) void hidden_kernel(
    const float* __restrict__ W1, const float* __restrict__ b1)
{
    const int j   = threadIdx.x & 63;
    const int grp = threadIdx.x >> 6;
    float wc[2 * HH];
#pragma unroll
    for (int k = 0; k < 2 * HH; k++) wc[k] = W1[k * HH + j];
    const float bj = b1[j];

    __shared__ __align__(16) float s_c[4][2 * HH];
    const int ntiles = BB / 4;
    for (int tile = blockIdx.x; tile < ntiles; tile += gridDim.x) {
        const int b = tile * 4 + grp;
        __syncthreads();
        s_c[grp][j]      = g_cat[b * 128 + j];
        s_c[grp][j + 64] = g_cat[b * 128 + j + 64];
        __syncthreads();
        float a0 = bj, a1 = 0.0f;
#pragma unroll
        for (int k = 0; k < 2 * HH; k += 8) {
            const float4 v = *reinterpret_cast<const float4*>(&s_c[grp][k]);
            const float4 w = *reinterpret_cast<const float4*>(&s_c[grp][k + 4]);
            a0 = fmaf(v.x, wc[k + 0], a0);
            a1 = fmaf(v.y, wc[k + 1], a1);
            a0 = fmaf(v.z, wc[k + 2], a0);
            a1 = fmaf(v.w, wc[k + 3], a1);
            a0 = fmaf(w.x, wc[k + 4], a0);
            a1 = fmaf(w.y, wc[k + 5], a1);
            a0 = fmaf(w.z, wc[k + 6], a0);
            a1 = fmaf(w.w, wc[k + 7], a1);
        }
        g_hid[b * HH + j] = fmaxf(a0 + a1, 0.0f);
    }
}

// ---------------- head: z, probs, loss -------------------------------------
__global__ void head_kernel(const float* __restrict__ W2, const float* __restrict__ b2,
                            const int* __restrict__ labels, float* __restrict__ out)
{
    const int warp = (blockIdx.x * blockDim.x + threadIdx.x) >> 5;
    const int lane = threadIdx.x & 31;
    if (warp >= BB) return;
    float acc = fmaf(g_hid[warp * HH + lane],      W2[lane],      0.0f);
    acc       = fmaf(g_hid[warp * HH + lane + 32], W2[lane + 32], acc);
#pragma unroll
    for (int s = 16; s; s >>= 1) acc += __shfl_xor_sync(0xffffffffu, acc, s);
    if (lane == 0) {
        const float z = acc + b2[0];
        out[warp] = 1.0f / (1.0f + __expf(-z));
        const float y = (float)labels[warp];
        const float t = (y > 0.5f) ? -z : z;
        const float sp = fmaxf(t, 0.0f) + log1pf(__expf(-fabsf(t)));
        atomicAdd(&g_loss, sp);
    }
}

__global__ void finalize_kernel(float* __restrict__ out)
{
    out[BB] = g_loss * (1.0f / (float)BB);
}

// ---------------------------------------------------------------------------
extern "C" void kernel_launch(void* const* d_in, const int* in_sizes, int n_in,
                              void* d_out, int out_size)
{
    const int*   emb_ind[2] = {(const int*)d_in[0],  (const int*)d_in[1]};
    const int*   adj[2]     = {(const int*)d_in[2],  (const int*)d_in[3]};
    const int*   prop[2]    = {(const int*)d_in[4],  (const int*)d_in[5]};
    const int*   labels     =  (const int*)d_in[6];
    const float* emb_table  =  (const float*)d_in[7];
    const float* Wp         =  (const float*)d_in[8];
    const float* bp         =  (const float*)d_in[9];
    const float* Wm[2]  = {(const float*)d_in[10], (const float*)d_in[16]};
    const float* bm[2]  = {(const float*)d_in[11], (const float*)d_in[17]};
    const float* Wih[2] = {(const float*)d_in[12], (const float*)d_in[18]};
    const float* Whh[2] = {(const float*)d_in[13], (const float*)d_in[19]};
    const float* bih[2] = {(const float*)d_in[14], (const float*)d_in[20]};
    const float* bhh[2] = {(const float*)d_in[15], (const float*)d_in[21]};
    const float* W1 = (const float*)d_in[22];
    const float* b1 = (const float*)d_in[23];
    const float* W2 = (const float*)d_in[24];
    const float* b2 = (const float*)d_in[25];
    float* out = (float*)d_out;

    init_kernel<<<(N2 * HH / 4 + 255) / 256, 256>>>();
    deg_kernel<<<(2 * EE + 255) / 256, 256>>>(adj[0], adj[1]);
    {
        dim3 fg(HH + 1, 2);
        fuse_kernel<<<fg, 192>>>(Wm[0], Wih[0], bm[0], Wm[1], Wih[1], bm[1]);
    }
    proj_kernel<<<2048, 256>>>(emb_table, emb_ind[0], emb_ind[1], Wp, bp);
    for (int l = 0; l < 2; l++) {
        for (int t = 0; t < 3; t++) {
            scatter_kernel<<<(2 * EE * 16) / 256, 256>>>(adj[0], adj[1]);
            gru_kernel<<<2048, 192>>>(Whh[l], bih[l], bhh[l], l);
        }
    }
    gather_kernel<<<(2 * BB * HH + 255) / 256, 256>>>(prop[0], prop[1]);
    hidden_kernel<<<512, 256>>>(W1, b1);
    head_kernel<<<(BB * 32 + 255) / 256, 256>>>(W2, b2, labels, out);
    finalize_kernel<<<1, 1>>>(out);
    (void)in_sizes; (void)n_in; (void)out_size;
}

// round 5
// speedup vs baseline: 1.3921x; 1.3208x over previous
#include <cuda_runtime.h>
#include <cuda_bf16.h>
#include <cstdint>
#include <math.h>

#define NN    100000
#define N2    200000
#define NPAD  200064          // 3126 * 64
#define NTILE 3126
#define EE    1200000
#define HH    64
#define EMBD  100
#define BB    4096

// ---------------- scratch (device globals; no allocation allowed) ----------
__device__ float g_ah[(size_t)NPAD * 128];     // per node: [agg(64) | h(64)]
__device__ float g_deg[NPAD];
__device__ float g_Wf[2 * 64 * 192];           // Wm@Wih per layer (fp32)
__device__ float g_bf[2 * 192];                // bm@Wih per layer
__device__ __nv_bfloat16 g_Bhi[2 * 256 * 128]; // fused B hi, [N=256][K=128]
__device__ __nv_bfloat16 g_Blo[2 * 256 * 128]; // fused B lo
__device__ float g_cat[BB * 128];
__device__ float g_hid[BB * 64];
__device__ float g_loss;

// ---------------- helpers ---------------------------------------------------
__device__ __forceinline__ uint32_t smem_u32(const void* p) {
    uint32_t a;
    asm("{ .reg .u64 t; cvta.to.shared.u64 t, %1; cvt.u32.u64 %0, t; }" : "=r"(a) : "l"(p));
    return a;
}
__device__ __forceinline__ uint32_t lds32(uint32_t addr) {
    uint32_t v;
    asm volatile("ld.shared.b32 %0, [%1];" : "=r"(v) : "r"(addr));
    return v;
}
__device__ __forceinline__ void mma16816(float* d, const uint32_t* a,
                                         uint32_t b0, uint32_t b1) {
    asm volatile(
        "mma.sync.aligned.m16n8k16.row.col.f32.bf16.bf16.f32 "
        "{%0,%1,%2,%3},{%4,%5,%6,%7},{%8,%9},{%0,%1,%2,%3};"
        : "+f"(d[0]), "+f"(d[1]), "+f"(d[2]), "+f"(d[3])
        : "r"(a[0]), "r"(a[1]), "r"(a[2]), "r"(a[3]), "r"(b0), "r"(b1));
}

// ---------------- init ------------------------------------------------------
__global__ void init_kernel()
{
    const size_t idx = (size_t)blockIdx.x * 256 + threadIdx.x;
    if (idx < (size_t)NPAD * 128 / 4)
        reinterpret_cast<float4*>(g_ah)[idx] = make_float4(0, 0, 0, 0);
    if (idx < NPAD) g_deg[idx] = 0.0f;
    if (idx == 0)   g_loss = 0.0f;
}

// ---------------- degree count ----------------------------------------------
__global__ void deg_kernel(const int* __restrict__ adj0, const int* __restrict__ adj1)
{
    const int e = blockIdx.x * 256 + threadIdx.x;
    if (e >= 2 * EE) return;
    const int tgt = (e < EE) ? adj0[2 * e + 1] : (adj1[2 * (e - EE) + 1] + NN);
    atomicAdd(&g_deg[tgt], 1.0f);
}

// ------------- fuse1: Wf = Wm@Wih, bf = bm@Wih ------------------------------
__global__ __launch_bounds__(192) void fuse1_kernel(
    const float* __restrict__ Wm0, const float* __restrict__ Wih0, const float* __restrict__ bm0,
    const float* __restrict__ Wm1, const float* __restrict__ Wih1, const float* __restrict__ bm1)
{
    const int k = blockIdx.x;           // 0..64 (64 => bias row)
    const int l = blockIdx.y;
    const int j = threadIdx.x;
    const float* Wm  = l ? Wm1  : Wm0;
    const float* Wih = l ? Wih1 : Wih0;
    const float* bm  = l ? bm1  : bm0;
    __shared__ float row[HH];
    if (j < HH) row[j] = (k < HH) ? Wm[k * HH + j] : bm[j];
    __syncthreads();
    float acc = 0.0f;
#pragma unroll
    for (int m = 0; m < HH; m++) acc = fmaf(row[m], Wih[m * 192 + j], acc);
    if (k < HH) g_Wf[l * HH * 192 + k * 192 + j] = acc;
    else        g_bf[l * 192 + j] = acc;
}

// ------------- fuse2: build fused B [128,256] -> bf16 hi/lo [256][128] ------
__global__ void fuse2_kernel(const float* __restrict__ Whh0, const float* __restrict__ Whh1)
{
    const int k = threadIdx.x;          // 0..127
    const int n = blockIdx.x;           // 0..255
    const int l = blockIdx.y;
    const float* Wf  = g_Wf + l * 64 * 192;
    const float* Whh = l ? Whh1 : Whh0;
    float v;
    if (n < 128)      v = (k < 64) ? Wf[k * 192 + n] : Whh[(k - 64) * 192 + n];
    else if (n < 192) v = (k < 64) ? Wf[k * 192 + n] : 0.0f;
    else              v = (k < 64) ? 0.0f            : Whh[(k - 64) * 192 + (n - 64)];
    const __nv_bfloat16 hi = __float2bfloat16(v);
    const __nv_bfloat16 lo = __float2bfloat16(v - __bfloat162float(hi));
    g_Bhi[l * 256 * 128 + n * 128 + k] = hi;
    g_Blo[l * 256 * 128 + n * 128 + k] = lo;
}

// -------- projection: h half of g_ah ----------------------------------------
__global__ __launch_bounds__(256) void proj_kernel(
    const float* __restrict__ emb,
    const int* __restrict__ ind0, const int* __restrict__ ind1,
    const float* __restrict__ Wp, const float* __restrict__ bp)
{
    const int j   = threadIdx.x & 63;
    const int grp = threadIdx.x >> 6;
    float wc[EMBD];
#pragma unroll
    for (int k = 0; k < EMBD; k++) wc[k] = Wp[k * HH + j];
    const float bj = bp[j];

    __shared__ __align__(16) float s_e[4][EMBD];
    const int ntiles = N2 / 4;
    for (int tile = blockIdx.x; tile < ntiles; tile += gridDim.x) {
        const int node = tile * 4 + grp;
        __syncthreads();
        {
            const int row = (node < NN) ? ind0[node] : ind1[node - NN];
            for (int k = j; k < EMBD; k += 64) s_e[grp][k] = emb[row * EMBD + k];
        }
        __syncthreads();
        float a0 = bj, a1 = 0.0f;
#pragma unroll
        for (int k = 0; k < 96; k += 8) {
            const float4 v = *reinterpret_cast<const float4*>(&s_e[grp][k]);
            const float4 w = *reinterpret_cast<const float4*>(&s_e[grp][k + 4]);
            a0 = fmaf(v.x, wc[k + 0], a0);
            a1 = fmaf(v.y, wc[k + 1], a1);
            a0 = fmaf(v.z, wc[k + 2], a0);
            a1 = fmaf(v.w, wc[k + 3], a1);
            a0 = fmaf(w.x, wc[k + 4], a0);
            a1 = fmaf(w.y, wc[k + 5], a1);
            a0 = fmaf(w.z, wc[k + 6], a0);
            a1 = fmaf(w.w, wc[k + 7], a1);
        }
        {
            const float4 v = *reinterpret_cast<const float4*>(&s_e[grp][96]);
            a0 = fmaf(v.x, wc[96], a0);
            a1 = fmaf(v.y, wc[97], a1);
            a0 = fmaf(v.z, wc[98], a0);
            a1 = fmaf(v.w, wc[99], a1);
        }
        g_ah[(size_t)node * 128 + 64 + j] = a0 + a1;
    }
}

// ---- scatter-add: agg half of g_ah += h half of src -----------------------
__global__ __launch_bounds__(256) void scatter_kernel(
    const int* __restrict__ adj0, const int* __restrict__ adj1)
{
    const int idx  = blockIdx.x * 256 + threadIdx.x;   // < 2*EE*16
    const int e    = idx >> 4;
    const int q    = idx & 15;
    const int lane = threadIdx.x & 31;
    long long ev = 0;
    if ((lane & 15) == 0) {
        ev = (e < EE) ? reinterpret_cast<const long long*>(adj0)[e]
                      : reinterpret_cast<const long long*>(adj1)[e - EE];
    }
    ev = __shfl_sync(0xffffffffu, ev, lane & 16);
    const int off = (e < EE) ? 0 : NN;
    const int src = (int)(ev & 0xffffffffll) + off;
    const int tgt = (int)(ev >> 32) + off;
    const float4 v = *reinterpret_cast<const float4*>(g_ah + (size_t)src * 128 + 64 + q * 4);
    float* dst = g_ah + (size_t)tgt * 128 + q * 4;
    asm volatile("red.global.add.v4.f32 [%0], {%1,%2,%3,%4};"
                 :: "l"(dst), "f"(v.x), "f"(v.y), "f"(v.z), "f"(v.w)
                 : "memory");
}

// ---------------- fused GEMM + GRU epilogue (mma.sync, bf16x3) --------------
// Per CTA: A = [64 nodes x 128 K], B = fused [256 x 128] -> D[64 x 256]
// cols 0:64 r-sum, 64:128 z-sum, 128:192 ig, 192:256 hg
// smem (bytes):
#define SM_BIAS  0                       // 448 floats
#define SM_AHI   2048                    // 64 x 272B
#define SM_ALO   19456
#define SM_BHI   36864                   // 256 x 272B
#define SM_BLO   106496
#define SM_TOTAL 176128
#define SM_D     2048                    // overlay: 64 x 264 f32 (67584B)

__global__ __launch_bounds__(256, 1) void gemm_gru_kernel(
    const float* __restrict__ bih, const float* __restrict__ bhh, int layer)
{
    extern __shared__ __align__(16) char smem[];
    const uint32_t sb  = smem_u32(smem);
    const int tid  = threadIdx.x;
    const int base = blockIdx.x * 64;

    // bias staging
    if (tid < 64) {
        float* bias = reinterpret_cast<float*>(smem + SM_BIAS);
        const int j = tid;
        bias[j]       = bih[j]       + bhh[j];        // r combined bias
        bias[64 + j]  = bih[64 + j]  + bhh[64 + j];   // z combined bias
        bias[128 + j] = bih[128 + j];                 // ig bias
        bias[192 + j] = bhh[128 + j];                 // hg bias
        const float* bf = g_bf + layer * 192;
        bias[256 + j] = bf[j];
        bias[320 + j] = bf[64 + j];
        bias[384 + j] = bf[128 + j];
    }

    // B tiles: [n][k] rows of 128 bf16, padded to 272B in smem
    {
        const uint4* bh = reinterpret_cast<const uint4*>(g_Bhi + layer * 256 * 128);
        const uint4* bl = reinterpret_cast<const uint4*>(g_Blo + layer * 256 * 128);
        for (int c = tid; c < 4096; c += 256) {
            const int n = c >> 4;
            const uint32_t off = (uint32_t)n * 272 + (c & 15) * 16;
            *reinterpret_cast<uint4*>(smem + SM_BHI + off) = bh[c];
            *reinterpret_cast<uint4*>(smem + SM_BLO + off) = bl[c];
        }
    }
    // A tile: fp32 -> hi/lo bf16, rows of 128 bf16 padded to 272B
    {
        const float4* ar = reinterpret_cast<const float4*>(g_ah + (size_t)base * 128);
        for (int c = tid; c < 2048; c += 256) {
            const float4 v = ar[c];
            const int m = c >> 5, k = (c & 31) << 2;
            __nv_bfloat16 h0 = __float2bfloat16(v.x);
            __nv_bfloat16 h1 = __float2bfloat16(v.y);
            __nv_bfloat16 h2 = __float2bfloat16(v.z);
            __nv_bfloat16 h3 = __float2bfloat16(v.w);
            __nv_bfloat16 l0 = __float2bfloat16(v.x - __bfloat162float(h0));
            __nv_bfloat16 l1 = __float2bfloat16(v.y - __bfloat162float(h1));
            __nv_bfloat16 l2 = __float2bfloat16(v.z - __bfloat162float(h2));
            __nv_bfloat16 l3 = __float2bfloat16(v.w - __bfloat162float(h3));
            uint2 hp, lp;
            hp.x = ((uint32_t)__bfloat16_as_ushort(h1) << 16) | __bfloat16_as_ushort(h0);
            hp.y = ((uint32_t)__bfloat16_as_ushort(h3) << 16) | __bfloat16_as_ushort(h2);
            lp.x = ((uint32_t)__bfloat16_as_ushort(l1) << 16) | __bfloat16_as_ushort(l0);
            lp.y = ((uint32_t)__bfloat16_as_ushort(l3) << 16) | __bfloat16_as_ushort(l2);
            const uint32_t off = (uint32_t)m * 272 + k * 2;
            *reinterpret_cast<uint2*>(smem + SM_AHI + off) = hp;
            *reinterpret_cast<uint2*>(smem + SM_ALO + off) = lp;
        }
    }
    __syncthreads();

    // warp tiling: 8 warps = 2(M) x 4(N); warp tile = 32 rows x 64 cols
    const int lane = tid & 31;
    const int warp = tid >> 5;
    const int wm = warp & 1;
    const int wn = warp >> 1;
    const int g = lane >> 2, t = lane & 3;

    float d[2][8][4];
#pragma unroll
    for (int a = 0; a < 2; a++)
#pragma unroll
        for (int b = 0; b < 8; b++)
#pragma unroll
            for (int c = 0; c < 4; c++) d[a][b][c] = 0.0f;

#pragma unroll
    for (int ks = 0; ks < 8; ks++) {
        const int k0 = ks * 16;
        uint32_t ahi[2][4], alo[2][4];
#pragma unroll
        for (int mt = 0; mt < 2; mt++) {
            const uint32_t r0 = (uint32_t)(wm * 32 + mt * 16 + g) * 272 + (k0 + 2 * t) * 2;
            ahi[mt][0] = lds32(sb + SM_AHI + r0);
            ahi[mt][1] = lds32(sb + SM_AHI + r0 + 8 * 272);
            ahi[mt][2] = lds32(sb + SM_AHI + r0 + 16);
            ahi[mt][3] = lds32(sb + SM_AHI + r0 + 8 * 272 + 16);
            alo[mt][0] = lds32(sb + SM_ALO + r0);
            alo[mt][1] = lds32(sb + SM_ALO + r0 + 8 * 272);
            alo[mt][2] = lds32(sb + SM_ALO + r0 + 16);
            alo[mt][3] = lds32(sb + SM_ALO + r0 + 8 * 272 + 16);
        }
#pragma unroll
        for (int nt = 0; nt < 8; nt++) {
            const uint32_t c0 = (uint32_t)(wn * 64 + nt * 8 + g) * 272 + (k0 + 2 * t) * 2;
            const uint32_t bh0 = lds32(sb + SM_BHI + c0);
            const uint32_t bh1 = lds32(sb + SM_BHI + c0 + 16);
            const uint32_t bl0 = lds32(sb + SM_BLO + c0);
            const uint32_t bl1 = lds32(sb + SM_BLO + c0 + 16);
#pragma unroll
            for (int mt = 0; mt < 2; mt++) {
                mma16816(d[mt][nt], ahi[mt], bh0, bh1);
                mma16816(d[mt][nt], ahi[mt], bl0, bl1);
                mma16816(d[mt][nt], alo[mt], bh0, bh1);
            }
        }
    }
    __syncthreads();

    // stage D to smem (overlay A/B region), stride 264 floats
    float* ds = reinterpret_cast<float*>(smem + SM_D);
#pragma unroll
    for (int mt = 0; mt < 2; mt++)
#pragma unroll
        for (int nt = 0; nt < 8; nt++) {
            const int row = wm * 32 + mt * 16 + g;
            const int col = wn * 64 + nt * 8 + 2 * t;
            *reinterpret_cast<float2*>(&ds[row * 264 + col]) =
                make_float2(d[mt][nt][0], d[mt][nt][1]);
            *reinterpret_cast<float2*>(&ds[(row + 8) * 264 + col]) =
                make_float2(d[mt][nt][2], d[mt][nt][3]);
        }
    __syncthreads();

    // GRU epilogue: gates -> h update, pre-zero agg
    const float* bias = reinterpret_cast<const float*>(smem + SM_BIAS);
    const int j = tid & 63;
#pragma unroll
    for (int it = 0; it < 16; it++) {
        const int i = (tid >> 6) + it * 4;         // node in tile: 0..63
        const size_t row = (size_t)base + i;
        const float deg  = g_deg[row];
        const float rsum = ds[i * 264 + j];
        const float zsum = ds[i * 264 + 64 + j];
        const float igs  = ds[i * 264 + 128 + j];
        const float hgs  = ds[i * 264 + 192 + j];
        const float hold = g_ah[row * 128 + 64 + j];
        const float r = 1.0f / (1.0f + __expf(-(rsum + bias[j]      + deg * bias[256 + j])));
        const float z = 1.0f / (1.0f + __expf(-(zsum + bias[64 + j] + deg * bias[320 + j])));
        const float ig = igs + bias[128 + j] + deg * bias[384 + j];
        const float hg = hgs + bias[192 + j];
        float nx = ig + r * hg;
        nx = fminf(fmaxf(nx, -15.0f), 15.0f);
        const float e2 = __expf(-2.0f * nx);
        const float nt = (1.0f - e2) / (1.0f + e2);
        g_ah[row * 128 + 64 + j] = (1.0f - z) * nt + z * hold;
        g_ah[row * 128 + j] = 0.0f;                // pre-zero agg for next scatter
    }
}

// ---------------- gather propagated nodes into concat buffer ---------------
__global__ void gather_kernel(const int* __restrict__ prop0,
                              const int* __restrict__ prop1)
{
    const int i = blockIdx.x * blockDim.x + threadIdx.x;
    if (i >= 2 * BB * HH) return;
    const int half = i / (BB * HH);
    const int r    = i - half * (BB * HH);
    const int b = r >> 6, j = r & 63;
    const int node = half ? (prop1[b] + NN) : prop0[b];
    g_cat[b * 128 + half * 64 + j] = g_ah[(size_t)node * 128 + 64 + j];
}

// ---------------- hidden = relu(cat @ W1 + b1) -----------------------------
__global__ __launch_bounds__(256) void hidden_kernel(
    const float* __restrict__ W1, const float* __restrict__ b1)
{
    const int j   = threadIdx.x & 63;
    const int grp = threadIdx.x >> 6;
    float wc[2 * HH];
#pragma unroll
    for (int k = 0; k < 2 * HH; k++) wc[k] = W1[k * HH + j];
    const float bj = b1[j];

    __shared__ __align__(16) float s_c[4][2 * HH];
    const int ntiles = BB / 4;
    for (int tile = blockIdx.x; tile < ntiles; tile += gridDim.x) {
        const int b = tile * 4 + grp;
        __syncthreads();
        s_c[grp][j]      = g_cat[b * 128 + j];
        s_c[grp][j + 64] = g_cat[b * 128 + j + 64];
        __syncthreads();
        float a0 = bj, a1 = 0.0f;
#pragma unroll
        for (int k = 0; k < 2 * HH; k += 8) {
            const float4 v = *reinterpret_cast<const float4*>(&s_c[grp][k]);
            const float4 w = *reinterpret_cast<const float4*>(&s_c[grp][k + 4]);
            a0 = fmaf(v.x, wc[k + 0], a0);
            a1 = fmaf(v.y, wc[k + 1], a1);
            a0 = fmaf(v.z, wc[k + 2], a0);
            a1 = fmaf(v.w, wc[k + 3], a1);
            a0 = fmaf(w.x, wc[k + 4], a0);
            a1 = fmaf(w.y, wc[k + 5], a1);
            a0 = fmaf(w.z, wc[k + 6], a0);
            a1 = fmaf(w.w, wc[k + 7], a1);
        }
        g_hid[b * HH + j] = fmaxf(a0 + a1, 0.0f);
    }
}

// ---------------- head: z, probs, loss -------------------------------------
__global__ void head_kernel(const float* __restrict__ W2, const float* __restrict__ b2,
                            const int* __restrict__ labels, float* __restrict__ out)
{
    const int warp = (blockIdx.x * blockDim.x + threadIdx.x) >> 5;
    const int lane = threadIdx.x & 31;
    if (warp >= BB) return;
    float acc = fmaf(g_hid[warp * HH + lane],      W2[lane],      0.0f);
    acc       = fmaf(g_hid[warp * HH + lane + 32], W2[lane + 32], acc);
#pragma unroll
    for (int s = 16; s; s >>= 1) acc += __shfl_xor_sync(0xffffffffu, acc, s);
    if (lane == 0) {
        const float z = acc + b2[0];
        out[warp] = 1.0f / (1.0f + __expf(-z));
        const float y = (float)labels[warp];
        const float t = (y > 0.5f) ? -z : z;
        const float sp = fmaxf(t, 0.0f) + log1pf(__expf(-fabsf(t)));
        atomicAdd(&g_loss, sp);
    }
}

__global__ void finalize_kernel(float* __restrict__ out)
{
    out[BB] = g_loss * (1.0f / (float)BB);
}

// ---------------------------------------------------------------------------
extern "C" void kernel_launch(void* const* d_in, const int* in_sizes, int n_in,
                              void* d_out, int out_size)
{
    const int*   emb_ind[2] = {(const int*)d_in[0],  (const int*)d_in[1]};
    const int*   adj[2]     = {(const int*)d_in[2],  (const int*)d_in[3]};
    const int*   prop[2]    = {(const int*)d_in[4],  (const int*)d_in[5]};
    const int*   labels     =  (const int*)d_in[6];
    const float* emb_table  =  (const float*)d_in[7];
    const float* Wp         =  (const float*)d_in[8];
    const float* bp         =  (const float*)d_in[9];
    const float* Wm[2]  = {(const float*)d_in[10], (const float*)d_in[16]};
    const float* bm[2]  = {(const float*)d_in[11], (const float*)d_in[17]};
    const float* Wih[2] = {(const float*)d_in[12], (const float*)d_in[18]};
    const float* Whh[2] = {(const float*)d_in[13], (const float*)d_in[19]};
    const float* bih[2] = {(const float*)d_in[14], (const float*)d_in[20]};
    const float* bhh[2] = {(const float*)d_in[15], (const float*)d_in[21]};
    const float* W1 = (const float*)d_in[22];
    const float* b1 = (const float*)d_in[23];
    const float* W2 = (const float*)d_in[24];
    const float* b2 = (const float*)d_in[25];
    float* out = (float*)d_out;

    static bool attr_set = false;
    if (!attr_set) {
        cudaFuncSetAttribute(gemm_gru_kernel,
                             cudaFuncAttributeMaxDynamicSharedMemorySize, SM_TOTAL);
        attr_set = true;
    }

    init_kernel<<<(int)(((size_t)NPAD * 128 / 4 + 255) / 256), 256>>>();
    deg_kernel<<<(2 * EE + 255) / 256, 256>>>(adj[0], adj[1]);
    {
        dim3 fg(HH + 1, 2);
        fuse1_kernel<<<fg, 192>>>(Wm[0], Wih[0], bm[0], Wm[1], Wih[1], bm[1]);
    }
    {
        dim3 f2(256, 2);
        fuse2_kernel<<<f2, 128>>>(Whh[0], Whh[1]);
    }
    proj_kernel<<<2048, 256>>>(emb_table, emb_ind[0], emb_ind[1], Wp, bp);
    for (int l = 0; l < 2; l++) {
        for (int t = 0; t < 3; t++) {
            scatter_kernel<<<(2 * EE * 16) / 256, 256>>>(adj[0], adj[1]);
            gemm_gru_kernel<<<NTILE, 256, SM_TOTAL>>>(bih[l], bhh[l], l);
        }
    }
    gather_kernel<<<(2 * BB * HH + 255) / 256, 256>>>(prop[0], prop[1]);
    hidden_kernel<<<512, 256>>>(W1, b1);
    head_kernel<<<(BB * 32 + 255) / 256, 256>>>(W2, b2, labels, out);
    finalize_kernel<<<1, 1>>>(out);
    (void)in_sizes; (void)n_in; (void)out_size;
}

// round 6
// speedup vs baseline: 1.5337x; 1.1018x over previous
#include <cuda_runtime.h>
#include <cuda_bf16.h>
#include <cstdint>
#include <math.h>

#define NN    100000
#define N2    200000
#define NPAD  200064          // 3126 * 64
#define NTILE 3126
#define EE    1200000
#define HH    64
#define EMBD  100
#define BB    4096

// ---------------- scratch (device globals; no allocation allowed) ----------
__device__ float g_ah[(size_t)NPAD * 128];     // per node: [agg(64) | h(64)]
__device__ float g_deg[NPAD];
__device__ float g_Wf[2 * 64 * 192];           // Wm@Wih per layer (fp32)
__device__ float g_bf[2 * 192];                // bm@Wih per layer
__device__ __nv_bfloat16 g_Bhi[2 * 256 * 128]; // fused B hi, [N=256][K=128]
__device__ __nv_bfloat16 g_Blo[2 * 256 * 128]; // fused B lo
__device__ float g_cat[BB * 128];
__device__ float g_hid[BB * 64];
__device__ float g_loss;

// ---------------- helpers ---------------------------------------------------
__device__ __forceinline__ uint32_t smem_u32(const void* p) {
    uint32_t a;
    asm("{ .reg .u64 t; cvta.to.shared.u64 t, %1; cvt.u32.u64 %0, t; }" : "=r"(a) : "l"(p));
    return a;
}
__device__ __forceinline__ void ldsm4(uint32_t* r, uint32_t addr) {
    asm volatile("ldmatrix.sync.aligned.m8n8.x4.shared.b16 {%0,%1,%2,%3}, [%4];"
                 : "=r"(r[0]), "=r"(r[1]), "=r"(r[2]), "=r"(r[3]) : "r"(addr));
}
__device__ __forceinline__ void mma16816(float* d, const uint32_t* a,
                                         uint32_t b0, uint32_t b1) {
    asm volatile(
        "mma.sync.aligned.m16n8k16.row.col.f32.bf16.bf16.f32 "
        "{%0,%1,%2,%3},{%4,%5,%6,%7},{%8,%9},{%0,%1,%2,%3};"
        : "+f"(d[0]), "+f"(d[1]), "+f"(d[2]), "+f"(d[3])
        : "r"(a[0]), "r"(a[1]), "r"(a[2]), "r"(a[3]), "r"(b0), "r"(b1));
}

// ---------------- init ------------------------------------------------------
__global__ void init_kernel()
{
    const size_t idx = (size_t)blockIdx.x * 256 + threadIdx.x;
    if (idx < (size_t)NPAD * 128 / 4)
        reinterpret_cast<float4*>(g_ah)[idx] = make_float4(0, 0, 0, 0);
    if (idx < NPAD) g_deg[idx] = 0.0f;
    if (idx == 0)   g_loss = 0.0f;
}

// ---------------- degree count ----------------------------------------------
__global__ void deg_kernel(const int* __restrict__ adj0, const int* __restrict__ adj1)
{
    const int e = blockIdx.x * 256 + threadIdx.x;
    if (e >= 2 * EE) return;
    const int tgt = (e < EE) ? adj0[2 * e + 1] : (adj1[2 * (e - EE) + 1] + NN);
    atomicAdd(&g_deg[tgt], 1.0f);
}

// ------------- fuse1: Wf = Wm@Wih, bf = bm@Wih ------------------------------
__global__ __launch_bounds__(192) void fuse1_kernel(
    const float* __restrict__ Wm0, const float* __restrict__ Wih0, const float* __restrict__ bm0,
    const float* __restrict__ Wm1, const float* __restrict__ Wih1, const float* __restrict__ bm1)
{
    const int k = blockIdx.x;           // 0..64 (64 => bias row)
    const int l = blockIdx.y;
    const int j = threadIdx.x;
    const float* Wm  = l ? Wm1  : Wm0;
    const float* Wih = l ? Wih1 : Wih0;
    const float* bm  = l ? bm1  : bm0;
    __shared__ float row[HH];
    if (j < HH) row[j] = (k < HH) ? Wm[k * HH + j] : bm[j];
    __syncthreads();
    float acc = 0.0f;
#pragma unroll
    for (int m = 0; m < HH; m++) acc = fmaf(row[m], Wih[m * 192 + j], acc);
    if (k < HH) g_Wf[l * HH * 192 + k * 192 + j] = acc;
    else        g_bf[l * 192 + j] = acc;
}

// ------------- fuse2: build fused B [128,256] -> bf16 hi/lo [256][128] ------
__global__ void fuse2_kernel(const float* __restrict__ Whh0, const float* __restrict__ Whh1)
{
    const int k = threadIdx.x;          // 0..127
    const int n = blockIdx.x;           // 0..255
    const int l = blockIdx.y;
    const float* Wf  = g_Wf + l * 64 * 192;
    const float* Whh = l ? Whh1 : Whh0;
    float v;
    if (n < 128)      v = (k < 64) ? Wf[k * 192 + n] : Whh[(k - 64) * 192 + n];
    else if (n < 192) v = (k < 64) ? Wf[k * 192 + n] : 0.0f;
    else              v = (k < 64) ? 0.0f            : Whh[(k - 64) * 192 + (n - 64)];
    const __nv_bfloat16 hi = __float2bfloat16(v);
    const __nv_bfloat16 lo = __float2bfloat16(v - __bfloat162float(hi));
    g_Bhi[l * 256 * 128 + n * 128 + k] = hi;
    g_Blo[l * 256 * 128 + n * 128 + k] = lo;
}

// -------- projection: h half of g_ah ----------------------------------------
__global__ __launch_bounds__(256) void proj_kernel(
    const float* __restrict__ emb,
    const int* __restrict__ ind0, const int* __restrict__ ind1,
    const float* __restrict__ Wp, const float* __restrict__ bp)
{
    const int j   = threadIdx.x & 63;
    const int grp = threadIdx.x >> 6;
    float wc[EMBD];
#pragma unroll
    for (int k = 0; k < EMBD; k++) wc[k] = Wp[k * HH + j];
    const float bj = bp[j];

    __shared__ __align__(16) float s_e[4][EMBD];
    const int ntiles = N2 / 4;
    for (int tile = blockIdx.x; tile < ntiles; tile += gridDim.x) {
        const int node = tile * 4 + grp;
        __syncthreads();
        {
            const int row = (node < NN) ? ind0[node] : ind1[node - NN];
            for (int k = j; k < EMBD; k += 64) s_e[grp][k] = emb[row * EMBD + k];
        }
        __syncthreads();
        float a0 = bj, a1 = 0.0f;
#pragma unroll
        for (int k = 0; k < 96; k += 8) {
            const float4 v = *reinterpret_cast<const float4*>(&s_e[grp][k]);
            const float4 w = *reinterpret_cast<const float4*>(&s_e[grp][k + 4]);
            a0 = fmaf(v.x, wc[k + 0], a0);
            a1 = fmaf(v.y, wc[k + 1], a1);
            a0 = fmaf(v.z, wc[k + 2], a0);
            a1 = fmaf(v.w, wc[k + 3], a1);
            a0 = fmaf(w.x, wc[k + 4], a0);
            a1 = fmaf(w.y, wc[k + 5], a1);
            a0 = fmaf(w.z, wc[k + 6], a0);
            a1 = fmaf(w.w, wc[k + 7], a1);
        }
        {
            const float4 v = *reinterpret_cast<const float4*>(&s_e[grp][96]);
            a0 = fmaf(v.x, wc[96], a0);
            a1 = fmaf(v.y, wc[97], a1);
            a0 = fmaf(v.z, wc[98], a0);
            a1 = fmaf(v.w, wc[99], a1);
        }
        g_ah[(size_t)node * 128 + 64 + j] = a0 + a1;
    }
}

// ---- scatter-add: agg half of g_ah += h half of src -----------------------
__global__ __launch_bounds__(256) void scatter_kernel(
    const int* __restrict__ adj0, const int* __restrict__ adj1)
{
    const int idx  = blockIdx.x * 256 + threadIdx.x;   // < 2*EE*16
    const int e    = idx >> 4;
    const int q    = idx & 15;
    const int lane = threadIdx.x & 31;
    long long ev = 0;
    if ((lane & 15) == 0) {
        ev = (e < EE) ? reinterpret_cast<const long long*>(adj0)[e]
                      : reinterpret_cast<const long long*>(adj1)[e - EE];
    }
    ev = __shfl_sync(0xffffffffu, ev, lane & 16);
    const int off = (e < EE) ? 0 : NN;
    const int src = (int)(ev & 0xffffffffll) + off;
    const int tgt = (int)(ev >> 32) + off;
    const float4 v = *reinterpret_cast<const float4*>(g_ah + (size_t)src * 128 + 64 + q * 4);
    float* dst = g_ah + (size_t)tgt * 128 + q * 4;
    asm volatile("red.global.add.v4.f32 [%0], {%1,%2,%3,%4};"
                 :: "l"(dst), "f"(v.x), "f"(v.y), "f"(v.z), "f"(v.w)
                 : "memory");
}

// ---------------- fused GEMM + GRU epilogue (mma.sync + ldmatrix) -----------
// Per CTA: A = [64 nodes x 128 K], B = fused [256 x 128] -> D[64 x 256]
// Warp (wm, wn): rows wm*32+mt*16.., cols gate*64 + wn*16 + f*8 for all 4 gates
#define SM_BIAS  0                       // 448 floats
#define SM_AHI   2048                    // 64 x 272B
#define SM_ALO   19456
#define SM_BHI   36864                   // 256 x 272B
#define SM_BLO   106496
#define SM_TOTAL 176128

__global__ __launch_bounds__(256, 1) void gemm_gru_kernel(
    const float* __restrict__ bih, const float* __restrict__ bhh, int layer)
{
    extern __shared__ __align__(16) char smem[];
    const uint32_t sb  = smem_u32(smem);
    const int tid  = threadIdx.x;
    const int base = blockIdx.x * 64;

    // bias staging
    if (tid < 64) {
        float* bias = reinterpret_cast<float*>(smem + SM_BIAS);
        const int j = tid;
        bias[j]       = bih[j]       + bhh[j];        // r combined bias
        bias[64 + j]  = bih[64 + j]  + bhh[64 + j];   // z combined bias
        bias[128 + j] = bih[128 + j];                 // ig bias
        bias[192 + j] = bhh[128 + j];                 // hg bias
        const float* bf = g_bf + layer * 192;
        bias[256 + j] = bf[j];
        bias[320 + j] = bf[64 + j];
        bias[384 + j] = bf[128 + j];
    }

    // B tiles: [n][k] rows of 128 bf16, padded to 272B in smem
    {
        const uint4* bh = reinterpret_cast<const uint4*>(g_Bhi + layer * 256 * 128);
        const uint4* bl = reinterpret_cast<const uint4*>(g_Blo + layer * 256 * 128);
        for (int c = tid; c < 4096; c += 256) {
            const int n = c >> 4;
            const uint32_t off = (uint32_t)n * 272 + (c & 15) * 16;
            *reinterpret_cast<uint4*>(smem + SM_BHI + off) = bh[c];
            *reinterpret_cast<uint4*>(smem + SM_BLO + off) = bl[c];
        }
    }
    // A tile: fp32 -> hi/lo bf16, rows of 128 bf16 padded to 272B
    {
        const float4* ar = reinterpret_cast<const float4*>(g_ah + (size_t)base * 128);
        for (int c = tid; c < 2048; c += 256) {
            const float4 v = ar[c];
            const int m = c >> 5, k = (c & 31) << 2;
            __nv_bfloat16 h0 = __float2bfloat16(v.x);
            __nv_bfloat16 h1 = __float2bfloat16(v.y);
            __nv_bfloat16 h2 = __float2bfloat16(v.z);
            __nv_bfloat16 h3 = __float2bfloat16(v.w);
            __nv_bfloat16 l0 = __float2bfloat16(v.x - __bfloat162float(h0));
            __nv_bfloat16 l1 = __float2bfloat16(v.y - __bfloat162float(h1));
            __nv_bfloat16 l2 = __float2bfloat16(v.z - __bfloat162float(h2));
            __nv_bfloat16 l3 = __float2bfloat16(v.w - __bfloat162float(h3));
            uint2 hp, lp;
            hp.x = ((uint32_t)__bfloat16_as_ushort(h1) << 16) | __bfloat16_as_ushort(h0);
            hp.y = ((uint32_t)__bfloat16_as_ushort(h3) << 16) | __bfloat16_as_ushort(h2);
            lp.x = ((uint32_t)__bfloat16_as_ushort(l1) << 16) | __bfloat16_as_ushort(l0);
            lp.y = ((uint32_t)__bfloat16_as_ushort(l3) << 16) | __bfloat16_as_ushort(l2);
            const uint32_t off = (uint32_t)m * 272 + k * 2;
            *reinterpret_cast<uint2*>(smem + SM_AHI + off) = hp;
            *reinterpret_cast<uint2*>(smem + SM_ALO + off) = lp;
        }
    }
    __syncthreads();

    const int lane = tid & 31;
    const int warp = tid >> 5;
    const int wm = warp & 1;             // M half (32 rows)
    const int wn = warp >> 1;            // 16-col slice within each gate group
    const int lg = lane >> 3, lr = lane & 7;

    // ldmatrix lane address offsets
    const int a_m = lr + (lg & 1) * 8;        // + k offset (lg>>1)*8
    const int a_k = (lg >> 1) * 8;
    const int b_n = lr + (lg >> 1) * 8;       // + k offset (lg&1)*8
    const int b_k = (lg & 1) * 8;

    float d[2][4][2][4];                 // [mt][gate][f][frag]
#pragma unroll
    for (int a = 0; a < 2; a++)
#pragma unroll
        for (int b = 0; b < 4; b++)
#pragma unroll
            for (int c = 0; c < 2; c++)
#pragma unroll
                for (int e = 0; e < 4; e++) d[a][b][c][e] = 0.0f;

#pragma unroll
    for (int ks = 0; ks < 8; ks++) {
        const int k0 = ks * 16;
        uint32_t ahi[2][4], alo[2][4];
#pragma unroll
        for (int mt = 0; mt < 2; mt++) {
            const uint32_t ra = (uint32_t)(wm * 32 + mt * 16 + a_m) * 272 + (k0 + a_k) * 2;
            ldsm4(ahi[mt], sb + SM_AHI + ra);
            ldsm4(alo[mt], sb + SM_ALO + ra);
        }
#pragma unroll
        for (int gate = 0; gate < 4; gate++) {
            const uint32_t rb = (uint32_t)(gate * 64 + wn * 16 + b_n) * 272 + (k0 + b_k) * 2;
            uint32_t bhi[4], blo[4];
            ldsm4(bhi, sb + SM_BHI + rb);
            ldsm4(blo, sb + SM_BLO + rb);
#pragma unroll
            for (int mt = 0; mt < 2; mt++) {
#pragma unroll
                for (int f = 0; f < 2; f++) {
                    mma16816(d[mt][gate][f], ahi[mt], bhi[f * 2], bhi[f * 2 + 1]);
                    mma16816(d[mt][gate][f], ahi[mt], blo[f * 2], blo[f * 2 + 1]);
                    mma16816(d[mt][gate][f], alo[mt], bhi[f * 2], bhi[f * 2 + 1]);
                }
            }
        }
    }

    // -------- register-resident GRU epilogue --------
    const float* bias = reinterpret_cast<const float*>(smem + SM_BIAS);
    const int g = lane >> 2, t = lane & 3;
    float degv[2][2];
#pragma unroll
    for (int mt = 0; mt < 2; mt++)
#pragma unroll
        for (int rr = 0; rr < 2; rr++)
            degv[mt][rr] = g_deg[(size_t)base + wm * 32 + mt * 16 + rr * 8 + g];

#pragma unroll
    for (int f = 0; f < 2; f++) {
        const int c = wn * 16 + f * 8 + 2 * t;
        const float br0 = bias[c],       br1 = bias[c + 1];
        const float bz0 = bias[64 + c],  bz1 = bias[64 + c + 1];
        const float bg0 = bias[128 + c], bg1 = bias[128 + c + 1];
        const float bh0 = bias[192 + c], bh1 = bias[192 + c + 1];
        const float fr0 = bias[256 + c], fr1 = bias[256 + c + 1];
        const float fz0 = bias[320 + c], fz1 = bias[320 + c + 1];
        const float fg0 = bias[384 + c], fg1 = bias[384 + c + 1];
#pragma unroll
        for (int mt = 0; mt < 2; mt++) {
#pragma unroll
            for (int rr = 0; rr < 2; rr++) {
                const size_t grow = (size_t)base + wm * 32 + mt * 16 + rr * 8 + g;
                const float deg = degv[mt][rr];
                const int idx = rr * 2;
                const float2 hold = *reinterpret_cast<const float2*>(g_ah + grow * 128 + 64 + c);
                const float r0 = 1.0f / (1.0f + __expf(-(d[mt][0][f][idx]     + br0 + deg * fr0)));
                const float r1 = 1.0f / (1.0f + __expf(-(d[mt][0][f][idx + 1] + br1 + deg * fr1)));
                const float z0 = 1.0f / (1.0f + __expf(-(d[mt][1][f][idx]     + bz0 + deg * fz0)));
                const float z1 = 1.0f / (1.0f + __expf(-(d[mt][1][f][idx + 1] + bz1 + deg * fz1)));
                const float ig0 = d[mt][2][f][idx]     + bg0 + deg * fg0;
                const float ig1 = d[mt][2][f][idx + 1] + bg1 + deg * fg1;
                const float hg0 = d[mt][3][f][idx]     + bh0;
                const float hg1 = d[mt][3][f][idx + 1] + bh1;
                float nx0 = ig0 + r0 * hg0;
                float nx1 = ig1 + r1 * hg1;
                nx0 = fminf(fmaxf(nx0, -15.0f), 15.0f);
                nx1 = fminf(fmaxf(nx1, -15.0f), 15.0f);
                const float e20 = __expf(-2.0f * nx0);
                const float e21 = __expf(-2.0f * nx1);
                const float n0 = (1.0f - e20) / (1.0f + e20);
                const float n1 = (1.0f - e21) / (1.0f + e21);
                float2 hn;
                hn.x = (1.0f - z0) * n0 + z0 * hold.x;
                hn.y = (1.0f - z1) * n1 + z1 * hold.y;
                *reinterpret_cast<float2*>(g_ah + grow * 128 + 64 + c) = hn;
                *reinterpret_cast<float2*>(g_ah + grow * 128 + c) = make_float2(0.0f, 0.0f);
            }
        }
    }
}

// ---------------- gather propagated nodes into concat buffer ---------------
__global__ void gather_kernel(const int* __restrict__ prop0,
                              const int* __restrict__ prop1)
{
    const int i = blockIdx.x * blockDim.x + threadIdx.x;
    if (i >= 2 * BB * HH) return;
    const int half = i / (BB * HH);
    const int r    = i - half * (BB * HH);
    const int b = r >> 6, j = r & 63;
    const int node = half ? (prop1[b] + NN) : prop0[b];
    g_cat[b * 128 + half * 64 + j] = g_ah[(size_t)node * 128 + 64 + j];
}

// ---------------- hidden = relu(cat @ W1 + b1) -----------------------------
__global__ __launch_bounds__(256) void hidden_kernel(
    const float* __restrict__ W1, const float* __restrict__ b1)
{
    const int j   = threadIdx.x & 63;
    const int grp = threadIdx.x >> 6;
    float wc[2 * HH];
#pragma unroll
    for (int k = 0; k < 2 * HH; k++) wc[k] = W1[k * HH + j];
    const float bj = b1[j];

    __shared__ __align__(16) float s_c[4][2 * HH];
    const int ntiles = BB / 4;
    for (int tile = blockIdx.x; tile < ntiles; tile += gridDim.x) {
        const int b = tile * 4 + grp;
        __syncthreads();
        s_c[grp][j]      = g_cat[b * 128 + j];
        s_c[grp][j + 64] = g_cat[b * 128 + j + 64];
        __syncthreads();
        float a0 = bj, a1 = 0.0f;
#pragma unroll
        for (int k = 0; k < 2 * HH; k += 8) {
            const float4 v = *reinterpret_cast<const float4*>(&s_c[grp][k]);
            const float4 w = *reinterpret_cast<const float4*>(&s_c[grp][k + 4]);
            a0 = fmaf(v.x, wc[k + 0], a0);
            a1 = fmaf(v.y, wc[k + 1], a1);
            a0 = fmaf(v.z, wc[k + 2], a0);
            a1 = fmaf(v.w, wc[k + 3], a1);
            a0 = fmaf(w.x, wc[k + 4], a0);
            a1 = fmaf(w.y, wc[k + 5], a1);
            a0 = fmaf(w.z, wc[k + 6], a0);
            a1 = fmaf(w.w, wc[k + 7], a1);
        }
        g_hid[b * HH + j] = fmaxf(a0 + a1, 0.0f);
    }
}

// ---------------- head: z, probs, loss -------------------------------------
__global__ void head_kernel(const float* __restrict__ W2, const float* __restrict__ b2,
                            const int* __restrict__ labels, float* __restrict__ out)
{
    const int warp = (blockIdx.x * blockDim.x + threadIdx.x) >> 5;
    const int lane = threadIdx.x & 31;
    if (warp >= BB) return;
    float acc = fmaf(g_hid[warp * HH + lane],      W2[lane],      0.0f);
    acc       = fmaf(g_hid[warp * HH + lane + 32], W2[lane + 32], acc);
#pragma unroll
    for (int s = 16; s; s >>= 1) acc += __shfl_xor_sync(0xffffffffu, acc, s);
    if (lane == 0) {
        const float z = acc + b2[0];
        out[warp] = 1.0f / (1.0f + __expf(-z));
        const float y = (float)labels[warp];
        const float t = (y > 0.5f) ? -z : z;
        const float sp = fmaxf(t, 0.0f) + log1pf(__expf(-fabsf(t)));
        atomicAdd(&g_loss, sp);
    }
}

__global__ void finalize_kernel(float* __restrict__ out)
{
    out[BB] = g_loss * (1.0f / (float)BB);
}

// ---------------------------------------------------------------------------
extern "C" void kernel_launch(void* const* d_in, const int* in_sizes, int n_in,
                              void* d_out, int out_size)
{
    const int*   emb_ind[2] = {(const int*)d_in[0],  (const int*)d_in[1]};
    const int*   adj[2]     = {(const int*)d_in[2],  (const int*)d_in[3]};
    const int*   prop[2]    = {(const int*)d_in[4],  (const int*)d_in[5]};
    const int*   labels     =  (const int*)d_in[6];
    const float* emb_table  =  (const float*)d_in[7];
    const float* Wp         =  (const float*)d_in[8];
    const float* bp         =  (const float*)d_in[9];
    const float* Wm[2]  = {(const float*)d_in[10], (const float*)d_in[16]};
    const float* bm[2]  = {(const float*)d_in[11], (const float*)d_in[17]};
    const float* Wih[2] = {(const float*)d_in[12], (const float*)d_in[18]};
    const float* Whh[2] = {(const float*)d_in[13], (const float*)d_in[19]};
    const float* bih[2] = {(const float*)d_in[14], (const float*)d_in[20]};
    const float* bhh[2] = {(const float*)d_in[15], (const float*)d_in[21]};
    const float* W1 = (const float*)d_in[22];
    const float* b1 = (const float*)d_in[23];
    const float* W2 = (const float*)d_in[24];
    const float* b2 = (const float*)d_in[25];
    float* out = (float*)d_out;

    static bool attr_set = false;
    if (!attr_set) {
        cudaFuncSetAttribute(gemm_gru_kernel,
                             cudaFuncAttributeMaxDynamicSharedMemorySize, SM_TOTAL);
        attr_set = true;
    }

    init_kernel<<<(int)(((size_t)NPAD * 128 / 4 + 255) / 256), 256>>>();
    deg_kernel<<<(2 * EE + 255) / 256, 256>>>(adj[0], adj[1]);
    {
        dim3 fg(HH + 1, 2);
        fuse1_kernel<<<fg, 192>>>(Wm[0], Wih[0], bm[0], Wm[1], Wih[1], bm[1]);
    }
    {
        dim3 f2(256, 2);
        fuse2_kernel<<<f2, 128>>>(Whh[0], Whh[1]);
    }
    proj_kernel<<<2048, 256>>>(emb_table, emb_ind[0], emb_ind[1], Wp, bp);
    for (int l = 0; l < 2; l++) {
        for (int t = 0; t < 3; t++) {
            scatter_kernel<<<(2 * EE * 16) / 256, 256>>>(adj[0], adj[1]);
            gemm_gru_kernel<<<NTILE, 256, SM_TOTAL>>>(bih[l], bhh[l], l);
        }
    }
    gather_kernel<<<(2 * BB * HH + 255) / 256, 256>>>(prop[0], prop[1]);
    hidden_kernel<<<512, 256>>>(W1, b1);
    head_kernel<<<(BB * 32 + 255) / 256, 256>>>(W2, b2, labels, out);
    finalize_kernel<<<1, 1>>>(out);
    (void)in_sizes; (void)n_in; (void)out_size;
}

// round 7
// speedup vs baseline: 1.9872x; 1.2957x over previous
#include <cuda_runtime.h>
#include <cuda_bf16.h>
#include <cstdint>
#include <math.h>

#define NN    100000
#define N2    200000
#define NPAD  200064          // 3126 * 64
#define NTILE 3126
#define EE    1200000
#define HH    64
#define EMBD  100
#define BB    4096

// ---------------- scratch (device globals; no allocation allowed) ----------
__device__ float g_ah[(size_t)NPAD * 128];     // per node: [agg(64) | h(64)]
__device__ float g_deg[NPAD];
__device__ float g_Wf[2 * 64 * 192];           // Wm@Wih per layer (fp32)
__device__ float g_bf[2 * 192];                // bm@Wih per layer
__device__ __nv_bfloat16 g_Bhi[2 * 256 * 128]; // fused B hi, [N=256][K=128]
__device__ __nv_bfloat16 g_Blo[2 * 256 * 128]; // fused B lo
__device__ float g_cat[BB * 128];
__device__ float g_hid[BB * 64];
__device__ float g_loss;

// ---------------- helpers ---------------------------------------------------
__device__ __forceinline__ uint32_t smem_u32(const void* p) {
    uint32_t a;
    asm("{ .reg .u64 t; cvta.to.shared.u64 t, %1; cvt.u32.u64 %0, t; }" : "=r"(a) : "l"(p));
    return a;
}
__device__ __forceinline__ void ldsm4(uint32_t* r, uint32_t addr) {
    asm volatile("ldmatrix.sync.aligned.m8n8.x4.shared.b16 {%0,%1,%2,%3}, [%4];"
                 : "=r"(r[0]), "=r"(r[1]), "=r"(r[2]), "=r"(r[3]) : "r"(addr));
}
__device__ __forceinline__ void mma16816(float* d, const uint32_t* a,
                                         uint32_t b0, uint32_t b1) {
    asm volatile(
        "mma.sync.aligned.m16n8k16.row.col.f32.bf16.bf16.f32 "
        "{%0,%1,%2,%3},{%4,%5,%6,%7},{%8,%9},{%0,%1,%2,%3};"
        : "+f"(d[0]), "+f"(d[1]), "+f"(d[2]), "+f"(d[3])
        : "r"(a[0]), "r"(a[1]), "r"(a[2]), "r"(a[3]), "r"(b0), "r"(b1));
}

// ---------------- init: deg + loss only ------------------------------------
__global__ void init_kernel()
{
    const int idx = blockIdx.x * 256 + threadIdx.x;
    if (idx < NPAD) g_deg[idx] = 0.0f;
    if (idx == 0)   g_loss = 0.0f;
}

// ---------------- degree count ----------------------------------------------
__global__ void deg_kernel(const int* __restrict__ adj0, const int* __restrict__ adj1)
{
    const int e = blockIdx.x * 256 + threadIdx.x;
    if (e >= 2 * EE) return;
    const int tgt = (e < EE) ? adj0[2 * e + 1] : (adj1[2 * (e - EE) + 1] + NN);
    atomicAdd(&g_deg[tgt], 1.0f);
}

// ------------- fuse1: Wf = Wm@Wih, bf = bm@Wih ------------------------------
__global__ __launch_bounds__(192) void fuse1_kernel(
    const float* __restrict__ Wm0, const float* __restrict__ Wih0, const float* __restrict__ bm0,
    const float* __restrict__ Wm1, const float* __restrict__ Wih1, const float* __restrict__ bm1)
{
    const int k = blockIdx.x;           // 0..64 (64 => bias row)
    const int l = blockIdx.y;
    const int j = threadIdx.x;
    const float* Wm  = l ? Wm1  : Wm0;
    const float* Wih = l ? Wih1 : Wih0;
    const float* bm  = l ? bm1  : bm0;
    __shared__ float row[HH];
    if (j < HH) row[j] = (k < HH) ? Wm[k * HH + j] : bm[j];
    __syncthreads();
    float acc = 0.0f;
#pragma unroll
    for (int m = 0; m < HH; m++) acc = fmaf(row[m], Wih[m * 192 + j], acc);
    if (k < HH) g_Wf[l * HH * 192 + k * 192 + j] = acc;
    else        g_bf[l * 192 + j] = acc;
}

// ------------- fuse2: build fused B [128,256] -> bf16 hi/lo [256][128] ------
__global__ void fuse2_kernel(const float* __restrict__ Whh0, const float* __restrict__ Whh1)
{
    const int k = threadIdx.x;          // 0..127
    const int n = blockIdx.x;           // 0..255
    const int l = blockIdx.y;
    const float* Wf  = g_Wf + l * 64 * 192;
    const float* Whh = l ? Whh1 : Whh0;
    float v;
    if (n < 128)      v = (k < 64) ? Wf[k * 192 + n] : Whh[(k - 64) * 192 + n];
    else if (n < 192) v = (k < 64) ? Wf[k * 192 + n] : 0.0f;
    else              v = (k < 64) ? 0.0f            : Whh[(k - 64) * 192 + (n - 64)];
    const __nv_bfloat16 hi = __float2bfloat16(v);
    const __nv_bfloat16 lo = __float2bfloat16(v - __bfloat162float(hi));
    g_Bhi[l * 256 * 128 + n * 128 + k] = hi;
    g_Blo[l * 256 * 128 + n * 128 + k] = lo;
}

// -------- projection: h half of g_ah (+ zero agg half) ----------------------
// 8 nodes per block-iteration; each thread-group handles 2 nodes (4 FMA chains)
__global__ __launch_bounds__(256) void proj_kernel(
    const float* __restrict__ emb,
    const int* __restrict__ ind0, const int* __restrict__ ind1,
    const float* __restrict__ Wp, const float* __restrict__ bp)
{
    const int j   = threadIdx.x & 63;
    const int grp = threadIdx.x >> 6;      // 0..3
    float wc[EMBD];
#pragma unroll
    for (int k = 0; k < EMBD; k++) wc[k] = Wp[k * HH + j];
    const float bj = bp[j];

    __shared__ __align__(16) float s_e[8][EMBD];
    const int ntiles = N2 / 8;             // 25000
    for (int tile = blockIdx.x; tile < ntiles; tile += gridDim.x) {
        const int nb = tile * 8;
        __syncthreads();
        for (int idx = threadIdx.x; idx < 8 * EMBD; idx += 256) {
            const int r = idx / EMBD, c = idx - r * EMBD;
            const int node = nb + r;
            const int row  = (node < NN) ? ind0[node] : ind1[node - NN];
            s_e[r][c] = emb[row * EMBD + c];
        }
        __syncthreads();
        const int n0 = nb + grp;
        const int n1 = n0 + 4;
        float a0 = bj, a1 = 0.0f, a2 = bj, a3 = 0.0f;
#pragma unroll
        for (int k = 0; k < 96; k += 8) {
            const float4 v = *reinterpret_cast<const float4*>(&s_e[grp][k]);
            const float4 w = *reinterpret_cast<const float4*>(&s_e[grp][k + 4]);
            const float4 u = *reinterpret_cast<const float4*>(&s_e[grp + 4][k]);
            const float4 x = *reinterpret_cast<const float4*>(&s_e[grp + 4][k + 4]);
            a0 = fmaf(v.x, wc[k + 0], a0);
            a2 = fmaf(u.x, wc[k + 0], a2);
            a1 = fmaf(v.y, wc[k + 1], a1);
            a3 = fmaf(u.y, wc[k + 1], a3);
            a0 = fmaf(v.z, wc[k + 2], a0);
            a2 = fmaf(u.z, wc[k + 2], a2);
            a1 = fmaf(v.w, wc[k + 3], a1);
            a3 = fmaf(u.w, wc[k + 3], a3);
            a0 = fmaf(w.x, wc[k + 4], a0);
            a2 = fmaf(x.x, wc[k + 4], a2);
            a1 = fmaf(w.y, wc[k + 5], a1);
            a3 = fmaf(x.y, wc[k + 5], a3);
            a0 = fmaf(w.z, wc[k + 6], a0);
            a2 = fmaf(x.z, wc[k + 6], a2);
            a1 = fmaf(w.w, wc[k + 7], a1);
            a3 = fmaf(x.w, wc[k + 7], a3);
        }
        {
            const float4 v = *reinterpret_cast<const float4*>(&s_e[grp][96]);
            const float4 u = *reinterpret_cast<const float4*>(&s_e[grp + 4][96]);
            a0 = fmaf(v.x, wc[96], a0);
            a2 = fmaf(u.x, wc[96], a2);
            a1 = fmaf(v.y, wc[97], a1);
            a3 = fmaf(u.y, wc[97], a3);
            a0 = fmaf(v.z, wc[98], a0);
            a2 = fmaf(u.z, wc[98], a2);
            a1 = fmaf(v.w, wc[99], a1);
            a3 = fmaf(u.w, wc[99], a3);
        }
        g_ah[(size_t)n0 * 128 + 64 + j] = a0 + a1;
        g_ah[(size_t)n0 * 128 + j]      = 0.0f;
        g_ah[(size_t)n1 * 128 + 64 + j] = a2 + a3;
        g_ah[(size_t)n1 * 128 + j]      = 0.0f;
    }
}

// ---- scatter-add: agg half of g_ah += h half of src -----------------------
__global__ __launch_bounds__(256) void scatter_kernel(
    const int* __restrict__ adj0, const int* __restrict__ adj1)
{
    const int idx  = blockIdx.x * 256 + threadIdx.x;   // < 2*EE*16
    const int e    = idx >> 4;
    const int q    = idx & 15;
    const int lane = threadIdx.x & 31;
    long long ev = 0;
    if ((lane & 15) == 0) {
        ev = (e < EE) ? reinterpret_cast<const long long*>(adj0)[e]
                      : reinterpret_cast<const long long*>(adj1)[e - EE];
    }
    ev = __shfl_sync(0xffffffffu, ev, lane & 16);
    const int off = (e < EE) ? 0 : NN;
    const int src = (int)(ev & 0xffffffffll) + off;
    const int tgt = (int)(ev >> 32) + off;
    const float4 v = *reinterpret_cast<const float4*>(g_ah + (size_t)src * 128 + 64 + q * 4);
    float* dst = g_ah + (size_t)tgt * 128 + q * 4;
    asm volatile("red.global.add.v4.f32 [%0], {%1,%2,%3,%4};"
                 :: "l"(dst), "f"(v.x), "f"(v.y), "f"(v.z), "f"(v.w)
                 : "memory");
}

// ------- persistent fused GEMM + GRU epilogue (mma.sync + ldmatrix) ---------
// B hi/lo + bias loaded ONCE per CTA; tiles processed grid-stride.
#define SM_BIAS  0                       // 448 floats
#define SM_AHI   2048                    // 64 x 272B
#define SM_ALO   19456
#define SM_BHI   36864                   // 256 x 272B
#define SM_BLO   106496
#define SM_TOTAL 176128
#define GGRID    152

__global__ __launch_bounds__(256, 1) void gemm_gru_kernel(
    const float* __restrict__ bih, const float* __restrict__ bhh, int layer)
{
    extern __shared__ __align__(16) char smem[];
    const uint32_t sb  = smem_u32(smem);
    const int tid  = threadIdx.x;

    // ---- one-time staging: bias + B hi/lo ----
    if (tid < 64) {
        float* bias = reinterpret_cast<float*>(smem + SM_BIAS);
        const int j = tid;
        bias[j]       = bih[j]       + bhh[j];
        bias[64 + j]  = bih[64 + j]  + bhh[64 + j];
        bias[128 + j] = bih[128 + j];
        bias[192 + j] = bhh[128 + j];
        const float* bf = g_bf + layer * 192;
        bias[256 + j] = bf[j];
        bias[320 + j] = bf[64 + j];
        bias[384 + j] = bf[128 + j];
    }
    {
        const uint4* bh = reinterpret_cast<const uint4*>(g_Bhi + layer * 256 * 128);
        const uint4* bl = reinterpret_cast<const uint4*>(g_Blo + layer * 256 * 128);
        for (int c = tid; c < 4096; c += 256) {
            const int n = c >> 4;
            const uint32_t off = (uint32_t)n * 272 + (c & 15) * 16;
            *reinterpret_cast<uint4*>(smem + SM_BHI + off) = bh[c];
            *reinterpret_cast<uint4*>(smem + SM_BLO + off) = bl[c];
        }
    }

    const int lane = tid & 31;
    const int warp = tid >> 5;
    const int wm = warp & 1;
    const int wn = warp >> 1;
    const int lg = lane >> 3, lr = lane & 7;
    const int a_m = lr + (lg & 1) * 8;
    const int a_k = (lg >> 1) * 8;
    const int b_n = lr + (lg >> 1) * 8;
    const int b_k = (lg & 1) * 8;
    const float* bias = reinterpret_cast<const float*>(smem + SM_BIAS);
    const int g = lane >> 2, t = lane & 3;

    __syncthreads();

    for (int tile = blockIdx.x; tile < NTILE; tile += GGRID) {
        const int base = tile * 64;

        // A tile: fp32 -> hi/lo bf16, rows of 128 bf16 padded to 272B
        {
            const float4* ar = reinterpret_cast<const float4*>(g_ah + (size_t)base * 128);
            for (int c = tid; c < 2048; c += 256) {
                const float4 v = ar[c];
                const int m = c >> 5, k = (c & 31) << 2;
                __nv_bfloat16 h0 = __float2bfloat16(v.x);
                __nv_bfloat16 h1 = __float2bfloat16(v.y);
                __nv_bfloat16 h2 = __float2bfloat16(v.z);
                __nv_bfloat16 h3 = __float2bfloat16(v.w);
                __nv_bfloat16 l0 = __float2bfloat16(v.x - __bfloat162float(h0));
                __nv_bfloat16 l1 = __float2bfloat16(v.y - __bfloat162float(h1));
                __nv_bfloat16 l2 = __float2bfloat16(v.z - __bfloat162float(h2));
                __nv_bfloat16 l3 = __float2bfloat16(v.w - __bfloat162float(h3));
                uint2 hp, lp;
                hp.x = ((uint32_t)__bfloat16_as_ushort(h1) << 16) | __bfloat16_as_ushort(h0);
                hp.y = ((uint32_t)__bfloat16_as_ushort(h3) << 16) | __bfloat16_as_ushort(h2);
                lp.x = ((uint32_t)__bfloat16_as_ushort(l1) << 16) | __bfloat16_as_ushort(l0);
                lp.y = ((uint32_t)__bfloat16_as_ushort(l3) << 16) | __bfloat16_as_ushort(l2);
                const uint32_t off = (uint32_t)m * 272 + k * 2;
                *reinterpret_cast<uint2*>(smem + SM_AHI + off) = hp;
                *reinterpret_cast<uint2*>(smem + SM_ALO + off) = lp;
            }
        }
        __syncthreads();

        float d[2][4][2][4];
#pragma unroll
        for (int a = 0; a < 2; a++)
#pragma unroll
            for (int b = 0; b < 4; b++)
#pragma unroll
                for (int c = 0; c < 2; c++)
#pragma unroll
                    for (int e = 0; e < 4; e++) d[a][b][c][e] = 0.0f;

#pragma unroll
        for (int ks = 0; ks < 8; ks++) {
            const int k0 = ks * 16;
            uint32_t ahi[2][4], alo[2][4];
#pragma unroll
            for (int mt = 0; mt < 2; mt++) {
                const uint32_t ra = (uint32_t)(wm * 32 + mt * 16 + a_m) * 272 + (k0 + a_k) * 2;
                ldsm4(ahi[mt], sb + SM_AHI + ra);
                ldsm4(alo[mt], sb + SM_ALO + ra);
            }
#pragma unroll
            for (int gate = 0; gate < 4; gate++) {
                const uint32_t rb = (uint32_t)(gate * 64 + wn * 16 + b_n) * 272 + (k0 + b_k) * 2;
                uint32_t bhi[4], blo[4];
                ldsm4(bhi, sb + SM_BHI + rb);
                ldsm4(blo, sb + SM_BLO + rb);
#pragma unroll
                for (int mt = 0; mt < 2; mt++) {
#pragma unroll
                    for (int f = 0; f < 2; f++) {
                        mma16816(d[mt][gate][f], ahi[mt], bhi[f * 2], bhi[f * 2 + 1]);
                        mma16816(d[mt][gate][f], ahi[mt], blo[f * 2], blo[f * 2 + 1]);
                        mma16816(d[mt][gate][f], alo[mt], bhi[f * 2], bhi[f * 2 + 1]);
                    }
                }
            }
        }

        // -------- register-resident GRU epilogue --------
        float degv[2][2];
#pragma unroll
        for (int mt = 0; mt < 2; mt++)
#pragma unroll
            for (int rr = 0; rr < 2; rr++)
                degv[mt][rr] = g_deg[(size_t)base + wm * 32 + mt * 16 + rr * 8 + g];

#pragma unroll
        for (int f = 0; f < 2; f++) {
            const int c = wn * 16 + f * 8 + 2 * t;
            const float br0 = bias[c],       br1 = bias[c + 1];
            const float bz0 = bias[64 + c],  bz1 = bias[64 + c + 1];
            const float bg0 = bias[128 + c], bg1 = bias[128 + c + 1];
            const float bh0 = bias[192 + c], bh1 = bias[192 + c + 1];
            const float fr0 = bias[256 + c], fr1 = bias[256 + c + 1];
            const float fz0 = bias[320 + c], fz1 = bias[320 + c + 1];
            const float fg0 = bias[384 + c], fg1 = bias[384 + c + 1];
#pragma unroll
            for (int mt = 0; mt < 2; mt++) {
#pragma unroll
                for (int rr = 0; rr < 2; rr++) {
                    const size_t grow = (size_t)base + wm * 32 + mt * 16 + rr * 8 + g;
                    const float deg = degv[mt][rr];
                    const int idx = rr * 2;
                    const float2 hold = *reinterpret_cast<const float2*>(g_ah + grow * 128 + 64 + c);
                    const float r0 = 1.0f / (1.0f + __expf(-(d[mt][0][f][idx]     + br0 + deg * fr0)));
                    const float r1 = 1.0f / (1.0f + __expf(-(d[mt][0][f][idx + 1] + br1 + deg * fr1)));
                    const float z0 = 1.0f / (1.0f + __expf(-(d[mt][1][f][idx]     + bz0 + deg * fz0)));
                    const float z1 = 1.0f / (1.0f + __expf(-(d[mt][1][f][idx + 1] + bz1 + deg * fz1)));
                    const float ig0 = d[mt][2][f][idx]     + bg0 + deg * fg0;
                    const float ig1 = d[mt][2][f][idx + 1] + bg1 + deg * fg1;
                    const float hg0 = d[mt][3][f][idx]     + bh0;
                    const float hg1 = d[mt][3][f][idx + 1] + bh1;
                    float nx0 = ig0 + r0 * hg0;
                    float nx1 = ig1 + r1 * hg1;
                    nx0 = fminf(fmaxf(nx0, -15.0f), 15.0f);
                    nx1 = fminf(fmaxf(nx1, -15.0f), 15.0f);
                    const float e20 = __expf(-2.0f * nx0);
                    const float e21 = __expf(-2.0f * nx1);
                    const float n0 = (1.0f - e20) / (1.0f + e20);
                    const float n1 = (1.0f - e21) / (1.0f + e21);
                    float2 hn;
                    hn.x = (1.0f - z0) * n0 + z0 * hold.x;
                    hn.y = (1.0f - z1) * n1 + z1 * hold.y;
                    *reinterpret_cast<float2*>(g_ah + grow * 128 + 64 + c) = hn;
                    *reinterpret_cast<float2*>(g_ah + grow * 128 + c) = make_float2(0.0f, 0.0f);
                }
            }
        }
        __syncthreads();   // guard A-smem overwrite next tile
    }
}

// ---------------- gather propagated nodes into concat buffer ---------------
__global__ void gather_kernel(const int* __restrict__ prop0,
                              const int* __restrict__ prop1)
{
    const int i = blockIdx.x * blockDim.x + threadIdx.x;
    if (i >= 2 * BB * HH) return;
    const int half = i / (BB * HH);
    const int r    = i - half * (BB * HH);
    const int b = r >> 6, j = r & 63;
    const int node = half ? (prop1[b] + NN) : prop0[b];
    g_cat[b * 128 + half * 64 + j] = g_ah[(size_t)node * 128 + 64 + j];
}

// ---------------- hidden = relu(cat @ W1 + b1) -----------------------------
__global__ __launch_bounds__(256) void hidden_kernel(
    const float* __restrict__ W1, const float* __restrict__ b1)
{
    const int j   = threadIdx.x & 63;
    const int grp = threadIdx.x >> 6;
    float wc[2 * HH];
#pragma unroll
    for (int k = 0; k < 2 * HH; k++) wc[k] = W1[k * HH + j];
    const float bj = b1[j];

    __shared__ __align__(16) float s_c[4][2 * HH];
    const int ntiles = BB / 4;
    for (int tile = blockIdx.x; tile < ntiles; tile += gridDim.x) {
        const int b = tile * 4 + grp;
        __syncthreads();
        s_c[grp][j]      = g_cat[b * 128 + j];
        s_c[grp][j + 64] = g_cat[b * 128 + j + 64];
        __syncthreads();
        float a0 = bj, a1 = 0.0f;
#pragma unroll
        for (int k = 0; k < 2 * HH; k += 8) {
            const float4 v = *reinterpret_cast<const float4*>(&s_c[grp][k]);
            const float4 w = *reinterpret_cast<const float4*>(&s_c[grp][k + 4]);
            a0 = fmaf(v.x, wc[k + 0], a0);
            a1 = fmaf(v.y, wc[k + 1], a1);
            a0 = fmaf(v.z, wc[k + 2], a0);
            a1 = fmaf(v.w, wc[k + 3], a1);
            a0 = fmaf(w.x, wc[k + 4], a0);
            a1 = fmaf(w.y, wc[k + 5], a1);
            a0 = fmaf(w.z, wc[k + 6], a0);
            a1 = fmaf(w.w, wc[k + 7], a1);
        }
        g_hid[b * HH + j] = fmaxf(a0 + a1, 0.0f);
    }
}

// ---------------- head: z, probs, loss -------------------------------------
__global__ void head_kernel(const float* __restrict__ W2, const float* __restrict__ b2,
                            const int* __restrict__ labels, float* __restrict__ out)
{
    const int warp = (blockIdx.x * blockDim.x + threadIdx.x) >> 5;
    const int lane = threadIdx.x & 31;
    if (warp >= BB) return;
    float acc = fmaf(g_hid[warp * HH + lane],      W2[lane],      0.0f);
    acc       = fmaf(g_hid[warp * HH + lane + 32], W2[lane + 32], acc);
#pragma unroll
    for (int s = 16; s; s >>= 1) acc += __shfl_xor_sync(0xffffffffu, acc, s);
    if (lane == 0) {
        const float z = acc + b2[0];
        out[warp] = 1.0f / (1.0f + __expf(-z));
        const float y = (float)labels[warp];
        const float t = (y > 0.5f) ? -z : z;
        const float sp = fmaxf(t, 0.0f) + log1pf(__expf(-fabsf(t)));
        atomicAdd(&g_loss, sp);
    }
}

__global__ void finalize_kernel(float* __restrict__ out)
{
    out[BB] = g_loss * (1.0f / (float)BB);
}

// ---------------------------------------------------------------------------
extern "C" void kernel_launch(void* const* d_in, const int* in_sizes, int n_in,
                              void* d_out, int out_size)
{
    const int*   emb_ind[2] = {(const int*)d_in[0],  (const int*)d_in[1]};
    const int*   adj[2]     = {(const int*)d_in[2],  (const int*)d_in[3]};
    const int*   prop[2]    = {(const int*)d_in[4],  (const int*)d_in[5]};
    const int*   labels     =  (const int*)d_in[6];
    const float* emb_table  =  (const float*)d_in[7];
    const float* Wp         =  (const float*)d_in[8];
    const float* bp         =  (const float*)d_in[9];
    const float* Wm[2]  = {(const float*)d_in[10], (const float*)d_in[16]};
    const float* bm[2]  = {(const float*)d_in[11], (const float*)d_in[17]};
    const float* Wih[2] = {(const float*)d_in[12], (const float*)d_in[18]};
    const float* Whh[2] = {(const float*)d_in[13], (const float*)d_in[19]};
    const float* bih[2] = {(const float*)d_in[14], (const float*)d_in[20]};
    const float* bhh[2] = {(const float*)d_in[15], (const float*)d_in[21]};
    const float* W1 = (const float*)d_in[22];
    const float* b1 = (const float*)d_in[23];
    const float* W2 = (const float*)d_in[24];
    const float* b2 = (const float*)d_in[25];
    float* out = (float*)d_out;

    static bool attr_set = false;
    if (!attr_set) {
        cudaFuncSetAttribute(gemm_gru_kernel,
                             cudaFuncAttributeMaxDynamicSharedMemorySize, SM_TOTAL);
        attr_set = true;
    }

    init_kernel<<<(NPAD + 255) / 256, 256>>>();
    deg_kernel<<<(2 * EE + 255) / 256, 256>>>(adj[0], adj[1]);
    {
        dim3 fg(HH + 1, 2);
        fuse1_kernel<<<fg, 192>>>(Wm[0], Wih[0], bm[0], Wm[1], Wih[1], bm[1]);
    }
    {
        dim3 f2(256, 2);
        fuse2_kernel<<<f2, 128>>>(Whh[0], Whh[1]);
    }
    proj_kernel<<<2048, 256>>>(emb_table, emb_ind[0], emb_ind[1], Wp, bp);
    for (int l = 0; l < 2; l++) {
        for (int t = 0; t < 3; t++) {
            scatter_kernel<<<(2 * EE * 16) / 256, 256>>>(adj[0], adj[1]);
            gemm_gru_kernel<<<GGRID, 256, SM_TOTAL>>>(bih[l], bhh[l], l);
        }
    }
    gather_kernel<<<(2 * BB * HH + 255) / 256, 256>>>(prop[0], prop[1]);
    hidden_kernel<<<512, 256>>>(W1, b1);
    head_kernel<<<(BB * 32 + 255) / 256, 256>>>(W2, b2, labels, out);
    finalize_kernel<<<1, 1>>>(out);
    (void)in_sizes; (void)n_in; (void)out_size;
}

// round 8
// speedup vs baseline: 2.5650x; 1.2908x over previous
#include <cuda_runtime.h>
#include <cuda_bf16.h>
#include <cstdint>
#include <math.h>

#define NN    100000
#define N2    200000
#define NPAD  200064          // 3126 * 64
#define NTILE 3126
#define EE    1200000
#define E2    (2 * EE)
#define HH    64
#define EMBD  100
#define BB    4096
#define SCAN_B 782            // ceil(NPAD/256)

// ---------------- scratch (device globals; no allocation allowed) ----------
__device__ float g_ah[(size_t)NPAD * 128];     // per node: [agg(64) | h(64)]
__device__ float g_deg[NPAD];
__device__ int   g_cnt[NPAD];
__device__ int   g_rp [NPAD + 1];              // CSR row ptr (by target)
__device__ int   g_cur[NPAD];                  // fill cursor
__device__ int   g_csr[E2];                    // CSR src indices
__device__ int   g_bsum[SCAN_B];
__device__ int   g_boff[SCAN_B];
__device__ float g_Wf[2 * 64 * 192];           // Wm@Wih per layer (fp32)
__device__ float g_bf[2 * 192];                // bm@Wih per layer
__device__ __nv_bfloat16 g_Bhi[2 * 256 * 128]; // fused B hi, [N=256][K=128]
__device__ __nv_bfloat16 g_Blo[2 * 256 * 128]; // fused B lo
__device__ float g_cat[BB * 128];
__device__ float g_hid[BB * 64];
__device__ float g_loss;

// ---------------- helpers ---------------------------------------------------
__device__ __forceinline__ uint32_t smem_u32(const void* p) {
    uint32_t a;
    asm("{ .reg .u64 t; cvta.to.shared.u64 t, %1; cvt.u32.u64 %0, t; }" : "=r"(a) : "l"(p));
    return a;
}
__device__ __forceinline__ void ldsm4(uint32_t* r, uint32_t addr) {
    asm volatile("ldmatrix.sync.aligned.m8n8.x4.shared.b16 {%0,%1,%2,%3}, [%4];"
                 : "=r"(r[0]), "=r"(r[1]), "=r"(r[2]), "=r"(r[3]) : "r"(addr));
}
__device__ __forceinline__ void mma16816(float* d, const uint32_t* a,
                                         uint32_t b0, uint32_t b1) {
    asm volatile(
        "mma.sync.aligned.m16n8k16.row.col.f32.bf16.bf16.f32 "
        "{%0,%1,%2,%3},{%4,%5,%6,%7},{%8,%9},{%0,%1,%2,%3};"
        : "+f"(d[0]), "+f"(d[1]), "+f"(d[2]), "+f"(d[3])
        : "r"(a[0]), "r"(a[1]), "r"(a[2]), "r"(a[3]), "r"(b0), "r"(b1));
}

// ---------------- init: zero counts + loss ----------------------------------
__global__ void init_kernel()
{
    const int idx = blockIdx.x * 256 + threadIdx.x;
    if (idx < NPAD) g_cnt[idx] = 0;
    if (idx == 0) { g_loss = 0.0f; g_rp[NPAD] = E2; }
}

// ---------------- degree count ----------------------------------------------
__global__ void deg_kernel(const int* __restrict__ adj0, const int* __restrict__ adj1)
{
    const int e = blockIdx.x * 256 + threadIdx.x;
    if (e >= E2) return;
    const int tgt = (e < EE) ? adj0[2 * e + 1] : (adj1[2 * (e - EE) + 1] + NN);
    atomicAdd(&g_cnt[tgt], 1);
}

// ---------------- prefix scan (3 kernels) -----------------------------------
__global__ void scan1_kernel()     // per-block sums
{
    __shared__ int s[256];
    const int i = blockIdx.x * 256 + threadIdx.x;
    s[threadIdx.x] = (i < NPAD) ? g_cnt[i] : 0;
    __syncthreads();
    for (int st = 128; st > 0; st >>= 1) {
        if (threadIdx.x < st) s[threadIdx.x] += s[threadIdx.x + st];
        __syncthreads();
    }
    if (threadIdx.x == 0) g_bsum[blockIdx.x] = s[0];
}

__global__ void scan2_kernel()     // exclusive scan of block sums (serial, once)
{
    if (threadIdx.x == 0) {
        int acc = 0;
        for (int b = 0; b < SCAN_B; b++) { g_boff[b] = acc; acc += g_bsum[b]; }
    }
}

__global__ void scan3_kernel()     // block exclusive scan + offset -> rp, cur, deg
{
    __shared__ int s[256];
    const int i = blockIdx.x * 256 + threadIdx.x;
    const int v = (i < NPAD) ? g_cnt[i] : 0;
    s[threadIdx.x] = v;
    __syncthreads();
    // Hillis-Steele inclusive scan
    int val = v;
    for (int st = 1; st < 256; st <<= 1) {
        int add = (threadIdx.x >= st) ? s[threadIdx.x - st] : 0;
        __syncthreads();
        val += add;
        s[threadIdx.x] = val;
        __syncthreads();
    }
    if (i < NPAD) {
        const int excl = g_boff[blockIdx.x] + val - v;
        g_rp [i] = excl;
        g_cur[i] = excl;
        g_deg[i] = (float)v;
    }
}

// ---------------- CSR fill ---------------------------------------------------
__global__ void fill_kernel(const int* __restrict__ adj0, const int* __restrict__ adj1)
{
    const int e = blockIdx.x * 256 + threadIdx.x;
    if (e >= E2) return;
    int src, tgt;
    if (e < EE) {
        const int2 st = reinterpret_cast<const int2*>(adj0)[e];
        src = st.x;       tgt = st.y;
    } else {
        const int2 st = reinterpret_cast<const int2*>(adj1)[e - EE];
        src = st.x + NN;  tgt = st.y + NN;
    }
    const int pos = atomicAdd(&g_cur[tgt], 1);
    g_csr[pos] = src;
}

// ------------- fuse1: Wf = Wm@Wih, bf = bm@Wih ------------------------------
__global__ __launch_bounds__(192) void fuse1_kernel(
    const float* __restrict__ Wm0, const float* __restrict__ Wih0, const float* __restrict__ bm0,
    const float* __restrict__ Wm1, const float* __restrict__ Wih1, const float* __restrict__ bm1)
{
    const int k = blockIdx.x;           // 0..64 (64 => bias row)
    const int l = blockIdx.y;
    const int j = threadIdx.x;
    const float* Wm  = l ? Wm1  : Wm0;
    const float* Wih = l ? Wih1 : Wih0;
    const float* bm  = l ? bm1  : bm0;
    __shared__ float row[HH];
    if (j < HH) row[j] = (k < HH) ? Wm[k * HH + j] : bm[j];
    __syncthreads();
    float acc = 0.0f;
#pragma unroll
    for (int m = 0; m < HH; m++) acc = fmaf(row[m], Wih[m * 192 + j], acc);
    if (k < HH) g_Wf[l * HH * 192 + k * 192 + j] = acc;
    else        g_bf[l * 192 + j] = acc;
}

// ------------- fuse2: build fused B [128,256] -> bf16 hi/lo [256][128] ------
__global__ void fuse2_kernel(const float* __restrict__ Whh0, const float* __restrict__ Whh1)
{
    const int k = threadIdx.x;          // 0..127
    const int n = blockIdx.x;           // 0..255
    const int l = blockIdx.y;
    const float* Wf  = g_Wf + l * 64 * 192;
    const float* Whh = l ? Whh1 : Whh0;
    float v;
    if (n < 128)      v = (k < 64) ? Wf[k * 192 + n] : Whh[(k - 64) * 192 + n];
    else if (n < 192) v = (k < 64) ? Wf[k * 192 + n] : 0.0f;
    else              v = (k < 64) ? 0.0f            : Whh[(k - 64) * 192 + (n - 64)];
    const __nv_bfloat16 hi = __float2bfloat16(v);
    const __nv_bfloat16 lo = __float2bfloat16(v - __bfloat162float(hi));
    g_Bhi[l * 256 * 128 + n * 128 + k] = hi;
    g_Blo[l * 256 * 128 + n * 128 + k] = lo;
}

// -------- projection: h half of g_ah ----------------------------------------
__global__ __launch_bounds__(256) void proj_kernel(
    const float* __restrict__ emb,
    const int* __restrict__ ind0, const int* __restrict__ ind1,
    const float* __restrict__ Wp, const float* __restrict__ bp)
{
    const int j   = threadIdx.x & 63;
    const int grp = threadIdx.x >> 6;      // 0..3
    float wc[EMBD];
#pragma unroll
    for (int k = 0; k < EMBD; k++) wc[k] = Wp[k * HH + j];
    const float bj = bp[j];

    __shared__ __align__(16) float s_e[8][EMBD];
    const int ntiles = N2 / 8;             // 25000
    for (int tile = blockIdx.x; tile < ntiles; tile += gridDim.x) {
        const int nb = tile * 8;
        __syncthreads();
        for (int idx = threadIdx.x; idx < 8 * EMBD; idx += 256) {
            const int r = idx / EMBD, c = idx - r * EMBD;
            const int node = nb + r;
            const int row  = (node < NN) ? ind0[node] : ind1[node - NN];
            s_e[r][c] = emb[row * EMBD + c];
        }
        __syncthreads();
        const int n0 = nb + grp;
        const int n1 = n0 + 4;
        float a0 = bj, a1 = 0.0f, a2 = bj, a3 = 0.0f;
#pragma unroll
        for (int k = 0; k < 96; k += 8) {
            const float4 v = *reinterpret_cast<const float4*>(&s_e[grp][k]);
            const float4 w = *reinterpret_cast<const float4*>(&s_e[grp][k + 4]);
            const float4 u = *reinterpret_cast<const float4*>(&s_e[grp + 4][k]);
            const float4 x = *reinterpret_cast<const float4*>(&s_e[grp + 4][k + 4]);
            a0 = fmaf(v.x, wc[k + 0], a0);
            a2 = fmaf(u.x, wc[k + 0], a2);
            a1 = fmaf(v.y, wc[k + 1], a1);
            a3 = fmaf(u.y, wc[k + 1], a3);
            a0 = fmaf(v.z, wc[k + 2], a0);
            a2 = fmaf(u.z, wc[k + 2], a2);
            a1 = fmaf(v.w, wc[k + 3], a1);
            a3 = fmaf(u.w, wc[k + 3], a3);
            a0 = fmaf(w.x, wc[k + 4], a0);
            a2 = fmaf(x.x, wc[k + 4], a2);
            a1 = fmaf(w.y, wc[k + 5], a1);
            a3 = fmaf(x.y, wc[k + 5], a3);
            a0 = fmaf(w.z, wc[k + 6], a0);
            a2 = fmaf(x.z, wc[k + 6], a2);
            a1 = fmaf(w.w, wc[k + 7], a1);
            a3 = fmaf(x.w, wc[k + 7], a3);
        }
        {
            const float4 v = *reinterpret_cast<const float4*>(&s_e[grp][96]);
            const float4 u = *reinterpret_cast<const float4*>(&s_e[grp + 4][96]);
            a0 = fmaf(v.x, wc[96], a0);
            a2 = fmaf(u.x, wc[96], a2);
            a1 = fmaf(v.y, wc[97], a1);
            a3 = fmaf(u.y, wc[97], a3);
            a0 = fmaf(v.z, wc[98], a0);
            a2 = fmaf(u.z, wc[98], a2);
            a1 = fmaf(v.w, wc[99], a1);
            a3 = fmaf(u.w, wc[99], a3);
        }
        g_ah[(size_t)n0 * 128 + 64 + j] = a0 + a1;
        g_ah[(size_t)n1 * 128 + 64 + j] = a2 + a3;
    }
}

// ---- pull-mode aggregation: agg[node] = sum_{src in CSR[node]} h[src] ------
// 16 lanes per node (one float4 per lane), 16 nodes per 256-thread block.
__global__ __launch_bounds__(256) void gsum_kernel()
{
    const int node = blockIdx.x * 16 + (threadIdx.x >> 4);
    const int q    = threadIdx.x & 15;
    if (node >= NPAD) return;
    const int s = g_rp[node];
    const int e = g_rp[node + 1];
    float4 a0 = make_float4(0, 0, 0, 0);
    float4 a1 = make_float4(0, 0, 0, 0);
    int i = s;
    for (; i + 1 < e; i += 2) {
        const int s0 = g_csr[i];
        const int s1 = g_csr[i + 1];
        const float4 v0 = *reinterpret_cast<const float4*>(g_ah + (size_t)s0 * 128 + 64 + q * 4);
        const float4 v1 = *reinterpret_cast<const float4*>(g_ah + (size_t)s1 * 128 + 64 + q * 4);
        a0.x += v0.x; a0.y += v0.y; a0.z += v0.z; a0.w += v0.w;
        a1.x += v1.x; a1.y += v1.y; a1.z += v1.z; a1.w += v1.w;
    }
    if (i < e) {
        const int s0 = g_csr[i];
        const float4 v0 = *reinterpret_cast<const float4*>(g_ah + (size_t)s0 * 128 + 64 + q * 4);
        a0.x += v0.x; a0.y += v0.y; a0.z += v0.z; a0.w += v0.w;
    }
    a0.x += a1.x; a0.y += a1.y; a0.z += a1.z; a0.w += a1.w;
    *reinterpret_cast<float4*>(g_ah + (size_t)node * 128 + q * 4) = a0;
}

// ------- persistent fused GEMM + GRU epilogue (mma.sync + ldmatrix) ---------
#define SM_BIAS  0                       // 448 floats
#define SM_AHI   2048                    // 64 x 272B
#define SM_ALO   19456
#define SM_BHI   36864                   // 256 x 272B
#define SM_BLO   106496
#define SM_TOTAL 176128
#define GGRID    152

__global__ __launch_bounds__(256, 1) void gemm_gru_kernel(
    const float* __restrict__ bih, const float* __restrict__ bhh, int layer)
{
    extern __shared__ __align__(16) char smem[];
    const uint32_t sb  = smem_u32(smem);
    const int tid  = threadIdx.x;

    // ---- one-time staging: bias + B hi/lo ----
    if (tid < 64) {
        float* bias = reinterpret_cast<float*>(smem + SM_BIAS);
        const int j = tid;
        bias[j]       = bih[j]       + bhh[j];
        bias[64 + j]  = bih[64 + j]  + bhh[64 + j];
        bias[128 + j] = bih[128 + j];
        bias[192 + j] = bhh[128 + j];
        const float* bf = g_bf + layer * 192;
        bias[256 + j] = bf[j];
        bias[320 + j] = bf[64 + j];
        bias[384 + j] = bf[128 + j];
    }
    {
        const uint4* bh = reinterpret_cast<const uint4*>(g_Bhi + layer * 256 * 128);
        const uint4* bl = reinterpret_cast<const uint4*>(g_Blo + layer * 256 * 128);
        for (int c = tid; c < 4096; c += 256) {
            const int n = c >> 4;
            const uint32_t off = (uint32_t)n * 272 + (c & 15) * 16;
            *reinterpret_cast<uint4*>(smem + SM_BHI + off) = bh[c];
            *reinterpret_cast<uint4*>(smem + SM_BLO + off) = bl[c];
        }
    }

    const int lane = tid & 31;
    const int warp = tid >> 5;
    const int wm = warp & 1;
    const int wn = warp >> 1;
    const int lg = lane >> 3, lr = lane & 7;
    const int a_m = lr + (lg & 1) * 8;
    const int a_k = (lg >> 1) * 8;
    const int b_n = lr + (lg >> 1) * 8;
    const int b_k = (lg & 1) * 8;
    const float* bias = reinterpret_cast<const float*>(smem + SM_BIAS);
    const int g = lane >> 2, t = lane & 3;

    __syncthreads();

    for (int tile = blockIdx.x; tile < NTILE; tile += GGRID) {
        const int base = tile * 64;

        // A tile: fp32 -> hi/lo bf16, rows of 128 bf16 padded to 272B
        {
            const float4* ar = reinterpret_cast<const float4*>(g_ah + (size_t)base * 128);
            for (int c = tid; c < 2048; c += 256) {
                const float4 v = ar[c];
                const int m = c >> 5, k = (c & 31) << 2;
                __nv_bfloat16 h0 = __float2bfloat16(v.x);
                __nv_bfloat16 h1 = __float2bfloat16(v.y);
                __nv_bfloat16 h2 = __float2bfloat16(v.z);
                __nv_bfloat16 h3 = __float2bfloat16(v.w);
                __nv_bfloat16 l0 = __float2bfloat16(v.x - __bfloat162float(h0));
                __nv_bfloat16 l1 = __float2bfloat16(v.y - __bfloat162float(h1));
                __nv_bfloat16 l2 = __float2bfloat16(v.z - __bfloat162float(h2));
                __nv_bfloat16 l3 = __float2bfloat16(v.w - __bfloat162float(h3));
                uint2 hp, lp;
                hp.x = ((uint32_t)__bfloat16_as_ushort(h1) << 16) | __bfloat16_as_ushort(h0);
                hp.y = ((uint32_t)__bfloat16_as_ushort(h3) << 16) | __bfloat16_as_ushort(h2);
                lp.x = ((uint32_t)__bfloat16_as_ushort(l1) << 16) | __bfloat16_as_ushort(l0);
                lp.y = ((uint32_t)__bfloat16_as_ushort(l3) << 16) | __bfloat16_as_ushort(l2);
                const uint32_t off = (uint32_t)m * 272 + k * 2;
                *reinterpret_cast<uint2*>(smem + SM_AHI + off) = hp;
                *reinterpret_cast<uint2*>(smem + SM_ALO + off) = lp;
            }
        }
        __syncthreads();

        float d[2][4][2][4];
#pragma unroll
        for (int a = 0; a < 2; a++)
#pragma unroll
            for (int b = 0; b < 4; b++)
#pragma unroll
                for (int c = 0; c < 2; c++)
#pragma unroll
                    for (int e = 0; e < 4; e++) d[a][b][c][e] = 0.0f;

#pragma unroll
        for (int ks = 0; ks < 8; ks++) {
            const int k0 = ks * 16;
            uint32_t ahi[2][4], alo[2][4];
#pragma unroll
            for (int mt = 0; mt < 2; mt++) {
                const uint32_t ra = (uint32_t)(wm * 32 + mt * 16 + a_m) * 272 + (k0 + a_k) * 2;
                ldsm4(ahi[mt], sb + SM_AHI + ra);
                ldsm4(alo[mt], sb + SM_ALO + ra);
            }
#pragma unroll
            for (int gate = 0; gate < 4; gate++) {
                const uint32_t rb = (uint32_t)(gate * 64 + wn * 16 + b_n) * 272 + (k0 + b_k) * 2;
                uint32_t bhi[4], blo[4];
                ldsm4(bhi, sb + SM_BHI + rb);
                ldsm4(blo, sb + SM_BLO + rb);
#pragma unroll
                for (int mt = 0; mt < 2; mt++) {
#pragma unroll
                    for (int f = 0; f < 2; f++) {
                        mma16816(d[mt][gate][f], ahi[mt], bhi[f * 2], bhi[f * 2 + 1]);
                        mma16816(d[mt][gate][f], ahi[mt], blo[f * 2], blo[f * 2 + 1]);
                        mma16816(d[mt][gate][f], alo[mt], bhi[f * 2], bhi[f * 2 + 1]);
                    }
                }
            }
        }

        // -------- register-resident GRU epilogue --------
        float degv[2][2];
#pragma unroll
        for (int mt = 0; mt < 2; mt++)
#pragma unroll
            for (int rr = 0; rr < 2; rr++)
                degv[mt][rr] = g_deg[(size_t)base + wm * 32 + mt * 16 + rr * 8 + g];

#pragma unroll
        for (int f = 0; f < 2; f++) {
            const int c = wn * 16 + f * 8 + 2 * t;
            const float br0 = bias[c],       br1 = bias[c + 1];
            const float bz0 = bias[64 + c],  bz1 = bias[64 + c + 1];
            const float bg0 = bias[128 + c], bg1 = bias[128 + c + 1];
            const float bh0 = bias[192 + c], bh1 = bias[192 + c + 1];
            const float fr0 = bias[256 + c], fr1 = bias[256 + c + 1];
            const float fz0 = bias[320 + c], fz1 = bias[320 + c + 1];
            const float fg0 = bias[384 + c], fg1 = bias[384 + c + 1];
#pragma unroll
            for (int mt = 0; mt < 2; mt++) {
#pragma unroll
                for (int rr = 0; rr < 2; rr++) {
                    const size_t grow = (size_t)base + wm * 32 + mt * 16 + rr * 8 + g;
                    const float deg = degv[mt][rr];
                    const int idx = rr * 2;
                    const float2 hold = *reinterpret_cast<const float2*>(g_ah + grow * 128 + 64 + c);
                    const float r0 = 1.0f / (1.0f + __expf(-(d[mt][0][f][idx]     + br0 + deg * fr0)));
                    const float r1 = 1.0f / (1.0f + __expf(-(d[mt][0][f][idx + 1] + br1 + deg * fr1)));
                    const float z0 = 1.0f / (1.0f + __expf(-(d[mt][1][f][idx]     + bz0 + deg * fz0)));
                    const float z1 = 1.0f / (1.0f + __expf(-(d[mt][1][f][idx + 1] + bz1 + deg * fz1)));
                    const float ig0 = d[mt][2][f][idx]     + bg0 + deg * fg0;
                    const float ig1 = d[mt][2][f][idx + 1] + bg1 + deg * fg1;
                    const float hg0 = d[mt][3][f][idx]     + bh0;
                    const float hg1 = d[mt][3][f][idx + 1] + bh1;
                    float nx0 = ig0 + r0 * hg0;
                    float nx1 = ig1 + r1 * hg1;
                    nx0 = fminf(fmaxf(nx0, -15.0f), 15.0f);
                    nx1 = fminf(fmaxf(nx1, -15.0f), 15.0f);
                    const float e20 = __expf(-2.0f * nx0);
                    const float e21 = __expf(-2.0f * nx1);
                    const float n0 = (1.0f - e20) / (1.0f + e20);
                    const float n1 = (1.0f - e21) / (1.0f + e21);
                    float2 hn;
                    hn.x = (1.0f - z0) * n0 + z0 * hold.x;
                    hn.y = (1.0f - z1) * n1 + z1 * hold.y;
                    *reinterpret_cast<float2*>(g_ah + grow * 128 + 64 + c) = hn;
                }
            }
        }
        __syncthreads();   // guard A-smem overwrite next tile
    }
}

// ---------------- gather propagated nodes into concat buffer ---------------
__global__ void gather_kernel(const int* __restrict__ prop0,
                              const int* __restrict__ prop1)
{
    const int i = blockIdx.x * blockDim.x + threadIdx.x;
    if (i >= 2 * BB * HH) return;
    const int half = i / (BB * HH);
    const int r    = i - half * (BB * HH);
    const int b = r >> 6, j = r & 63;
    const int node = half ? (prop1[b] + NN) : prop0[b];
    g_cat[b * 128 + half * 64 + j] = g_ah[(size_t)node * 128 + 64 + j];
}

// ---------------- hidden = relu(cat @ W1 + b1) -----------------------------
__global__ __launch_bounds__(256) void hidden_kernel(
    const float* __restrict__ W1, const float* __restrict__ b1)
{
    const int j   = threadIdx.x & 63;
    const int grp = threadIdx.x >> 6;
    float wc[2 * HH];
#pragma unroll
    for (int k = 0; k < 2 * HH; k++) wc[k] = W1[k * HH + j];
    const float bj = b1[j];

    __shared__ __align__(16) float s_c[4][2 * HH];
    const int ntiles = BB / 4;
    for (int tile = blockIdx.x; tile < ntiles; tile += gridDim.x) {
        const int b = tile * 4 + grp;
        __syncthreads();
        s_c[grp][j]      = g_cat[b * 128 + j];
        s_c[grp][j + 64] = g_cat[b * 128 + j + 64];
        __syncthreads();
        float a0 = bj, a1 = 0.0f;
#pragma unroll
        for (int k = 0; k < 2 * HH; k += 8) {
            const float4 v = *reinterpret_cast<const float4*>(&s_c[grp][k]);
            const float4 w = *reinterpret_cast<const float4*>(&s_c[grp][k + 4]);
            a0 = fmaf(v.x, wc[k + 0], a0);
            a1 = fmaf(v.y, wc[k + 1], a1);
            a0 = fmaf(v.z, wc[k + 2], a0);
            a1 = fmaf(v.w, wc[k + 3], a1);
            a0 = fmaf(w.x, wc[k + 4], a0);
            a1 = fmaf(w.y, wc[k + 5], a1);
            a0 = fmaf(w.z, wc[k + 6], a0);
            a1 = fmaf(w.w, wc[k + 7], a1);
        }
        g_hid[b * HH + j] = fmaxf(a0 + a1, 0.0f);
    }
}

// ---------------- head: z, probs, loss -------------------------------------
__global__ void head_kernel(const float* __restrict__ W2, const float* __restrict__ b2,
                            const int* __restrict__ labels, float* __restrict__ out)
{
    const int warp = (blockIdx.x * blockDim.x + threadIdx.x) >> 5;
    const int lane = threadIdx.x & 31;
    if (warp >= BB) return;
    float acc = fmaf(g_hid[warp * HH + lane],      W2[lane],      0.0f);
    acc       = fmaf(g_hid[warp * HH + lane + 32], W2[lane + 32], acc);
#pragma unroll
    for (int s = 16; s; s >>= 1) acc += __shfl_xor_sync(0xffffffffu, acc, s);
    if (lane == 0) {
        const float z = acc + b2[0];
        out[warp] = 1.0f / (1.0f + __expf(-z));
        const float y = (float)labels[warp];
        const float t = (y > 0.5f) ? -z : z;
        const float sp = fmaxf(t, 0.0f) + log1pf(__expf(-fabsf(t)));
        atomicAdd(&g_loss, sp);
    }
}

__global__ void finalize_kernel(float* __restrict__ out)
{
    out[BB] = g_loss * (1.0f / (float)BB);
}

// ---------------------------------------------------------------------------
extern "C" void kernel_launch(void* const* d_in, const int* in_sizes, int n_in,
                              void* d_out, int out_size)
{
    const int*   emb_ind[2] = {(const int*)d_in[0],  (const int*)d_in[1]};
    const int*   adj[2]     = {(const int*)d_in[2],  (const int*)d_in[3]};
    const int*   prop[2]    = {(const int*)d_in[4],  (const int*)d_in[5]};
    const int*   labels     =  (const int*)d_in[6];
    const float* emb_table  =  (const float*)d_in[7];
    const float* Wp         =  (const float*)d_in[8];
    const float* bp         =  (const float*)d_in[9];
    const float* Wm[2]  = {(const float*)d_in[10], (const float*)d_in[16]};
    const float* bm[2]  = {(const float*)d_in[11], (const float*)d_in[17]};
    const float* Wih[2] = {(const float*)d_in[12], (const float*)d_in[18]};
    const float* Whh[2] = {(const float*)d_in[13], (const float*)d_in[19]};
    const float* bih[2] = {(const float*)d_in[14], (const float*)d_in[20]};
    const float* bhh[2] = {(const float*)d_in[15], (const float*)d_in[21]};
    const float* W1 = (const float*)d_in[22];
    const float* b1 = (const float*)d_in[23];
    const float* W2 = (const float*)d_in[24];
    const float* b2 = (const float*)d_in[25];
    float* out = (float*)d_out;

    static bool attr_set = false;
    if (!attr_set) {
        cudaFuncSetAttribute(gemm_gru_kernel,
                             cudaFuncAttributeMaxDynamicSharedMemorySize, SM_TOTAL);
        attr_set = true;
    }

    init_kernel<<<(NPAD + 255) / 256, 256>>>();
    deg_kernel<<<(E2 + 255) / 256, 256>>>(adj[0], adj[1]);
    scan1_kernel<<<SCAN_B, 256>>>();
    scan2_kernel<<<1, 32>>>();
    scan3_kernel<<<SCAN_B, 256>>>();
    fill_kernel<<<(E2 + 255) / 256, 256>>>(adj[0], adj[1]);
    {
        dim3 fg(HH + 1, 2);
        fuse1_kernel<<<fg, 192>>>(Wm[0], Wih[0], bm[0], Wm[1], Wih[1], bm[1]);
    }
    {
        dim3 f2(256, 2);
        fuse2_kernel<<<f2, 128>>>(Whh[0], Whh[1]);
    }
    proj_kernel<<<2048, 256>>>(emb_table, emb_ind[0], emb_ind[1], Wp, bp);
    for (int l = 0; l < 2; l++) {
        for (int t = 0; t < 3; t++) {
            gsum_kernel<<<NPAD / 16, 256>>>();
            gemm_gru_kernel<<<GGRID, 256, SM_TOTAL>>>(bih[l], bhh[l], l);
        }
    }
    gather_kernel<<<(2 * BB * HH + 255) / 256, 256>>>(prop[0], prop[1]);
    hidden_kernel<<<512, 256>>>(W1, b1);
    head_kernel<<<(BB * 32 + 255) / 256, 256>>>(W2, b2, labels, out);
    finalize_kernel<<<1, 1>>>(out);
    (void)in_sizes; (void)n_in; (void)out_size;
}